// round 2
// baseline (speedup 1.0000x reference)
#include <cuda_runtime.h>

#define NLEAF 4096
#define NNODE 8191
#define NROW  8192
#define HID   512
#define HID4  128

#define OFF_EF     16382
#define OFF_EMB    16807932
#define OFF_FOCAL  21002236

typedef unsigned long long ULL;

// ----------------------------- scratch ---------------------------------------
__device__ float g_dW[NROW*HID];
__device__ float g_h[NROW*HID];
__device__ float g_agg[NROW*HID];
__device__ float g_X[(size_t)NNODE*1024];
__device__ float g_Z1[NNODE*HID];
__device__ float g_Z2[NNODE*HID];
__device__ float g_Bm[1024*HID];
__device__ float g_cvec[HID];
__device__ float g_hf[HID];
__device__ float g_c[NNODE];          // zero-init; leaves stay 0 forever
__device__ int   g_postF[NNODE];
__device__ int   g_preF[NNODE];

// ----------------------------- sync helpers ----------------------------------
__device__ __forceinline__ void st_rel(int* p, int v) {
    asm volatile("st.release.gpu.global.b32 [%0], %1;" :: "l"(p), "r"(v) : "memory");
}
__device__ __forceinline__ int ld_acq(const int* p) {
    int v;
    asm volatile("ld.acquire.gpu.global.b32 %0, [%1];" : "=r"(v) : "l"(p) : "memory");
    return v;
}

// ----------------------------- small kernels ---------------------------------
__global__ void k_reset() {
    int i = blockIdx.x * blockDim.x + threadIdx.x;
    if (i < 2*NNODE) {
        if (i < NNODE) g_postF[i] = 0;
        else           g_preF[i - NNODE] = 0;
    }
}

__global__ void k_leafinit(const int* __restrict__ ns, const int* __restrict__ focal,
                           const float* __restrict__ W1) {
    int b = blockIdx.x;                 // 0..NLEAF (last = focal row)
    int u, src;
    if (b == NLEAF) { u = NNODE; src = focal[0]; }
    else            { u = b; src = ns[b]; if (src < 0) return; }
    const float4* w = (const float4*)(W1 + (size_t)src*HID);
    float4* d = (float4*)(g_dW + (size_t)u*HID);
    d[threadIdx.x] = w[threadIdx.x];    // 128 threads * float4
}

__global__ void k_focalfeat(const int* __restrict__ focal, float* __restrict__ out) {
    int i = blockIdx.x * blockDim.x + threadIdx.x;
    if (i < NLEAF) out[OFF_FOCAL + i] = (i == focal[0]) ? 1.f : 0.f;
}

// ----------------------------- tree recursion --------------------------------
__global__ void k_tree(const int* __restrict__ ch0, const int* __restrict__ ch1,
                       const int* __restrict__ parent) {
    const int warps = gridDim.x * (blockDim.x >> 5);
    const int gw    = blockIdx.x * (blockDim.x >> 5) + (threadIdx.x >> 5);
    const int lane  = threadIdx.x & 31;
    const int NI    = NNODE - NLEAF;     // 4095
    const int root  = NNODE - 1;

    // -------- postorder (ascending ids) --------
    for (int i = gw; i < NI; i += warps) {
        int u = NLEAF + i;
        int a = ch0[u], b = ch1[u];
        if (a >= NLEAF) while (!ld_acq(&g_postF[a])) __nanosleep(40);
        if (b >= NLEAF) while (!ld_acq(&g_postF[b])) __nanosleep(40);
        __syncwarp();
        float cu = 1.f / (3.f - g_c[a] - g_c[b]);
        const float4* pa = (const float4*)(g_dW + (size_t)a*HID);
        const float4* pb = (const float4*)(g_dW + (size_t)b*HID);
        float4*       pu = (float4*)(g_dW + (size_t)u*HID);
        #pragma unroll
        for (int j = 0; j < 4; j++) {
            int c4 = lane + j*32;
            float4 x = pa[c4], y = pb[c4], r;
            r.x = cu*(x.x+y.x); r.y = cu*(x.y+y.y);
            r.z = cu*(x.z+y.z); r.w = cu*(x.w+y.w);
            pu[c4] = r;
        }
        if (lane == 0) g_c[u] = cu;
        __threadfence();
        __syncwarp();
        if (lane == 0) {
            st_rel(&g_postF[u], 1);
            if (u == root) st_rel(&g_preF[u], 1);   // root: final = post
        }
        __syncwarp();
    }

    // -------- preorder (descending ids) --------
    for (int i = NI - 1 - gw; i >= 0; i -= warps) {
        int u = NLEAF + i;
        if (u == root) continue;
        int p = parent[u];
        while (!ld_acq(&g_postF[u])) __nanosleep(40);
        while (!ld_acq(&g_preF[p]))  __nanosleep(40);
        __syncwarp();
        float cu = g_c[u];
        const float4* pp = (const float4*)(g_dW + (size_t)p*HID);
        float4*       pu = (float4*)(g_dW + (size_t)u*HID);
        #pragma unroll
        for (int j = 0; j < 4; j++) {
            int c4 = lane + j*32;
            float4 x = pp[c4], r = pu[c4];
            r.x += cu*x.x; r.y += cu*x.y; r.z += cu*x.z; r.w += cu*x.w;
            pu[c4] = r;
        }
        __threadfence();
        __syncwarp();
        if (lane == 0) st_rel(&g_preF[u], 1);
        __syncwarp();
    }
}

// ----------------------------- GCN aggregation -------------------------------
__global__ void k_agg(int phase, const int* __restrict__ neigh,
                      const float* __restrict__ bias) {
    const float* src = (phase == 0) ? g_dW : g_h;
    float*       dst = (phase == 0) ? g_h  : g_agg;
    int u = blockIdx.x;
    int n0 = neigh[3*u], n1 = neigh[3*u+1], n2 = neigh[3*u+2];
    float inv = 1.f / (1.f + (n0 >= 0) + (n1 >= 0) + (n2 >= 0));
    const float4* s  = (const float4*)(src + (size_t)u*HID);
    const float4* p0 = (const float4*)(src + (size_t)(n0 >= 0 ? n0 : 0)*HID);
    const float4* p1 = (const float4*)(src + (size_t)(n1 >= 0 ? n1 : 0)*HID);
    const float4* p2 = (const float4*)(src + (size_t)(n2 >= 0 ? n2 : 0)*HID);
    float4* d = (float4*)(dst + (size_t)u*HID);
    int j = threadIdx.x;                  // 128 threads, HID4 = 128
    float4 v = s[j];
    if (n0 >= 0) { float4 t = p0[j]; v.x += t.x; v.y += t.y; v.z += t.z; v.w += t.w; }
    if (n1 >= 0) { float4 t = p1[j]; v.x += t.x; v.y += t.y; v.z += t.z; v.w += t.w; }
    if (n2 >= 0) { float4 t = p2[j]; v.x += t.x; v.y += t.y; v.z += t.z; v.w += t.w; }
    v.x *= inv; v.y *= inv; v.z *= inv; v.w *= inv;
    if (phase == 0) {
        float4 b = ((const float4*)bias)[j];
        v.x = fmaxf(v.x + b.x, 0.f); v.y = fmaxf(v.y + b.y, 0.f);
        v.z = fmaxf(v.z + b.z, 0.f); v.w = fmaxf(v.w + b.w, 0.f);
    }
    d[j] = v;
}

// ----------------------------- f32x2 SGEMM -----------------------------------
__device__ __forceinline__ void fma2(ULL &d, ULL a, ULL b) {
    asm("fma.rn.f32x2 %0, %1, %2, %0;" : "+l"(d) : "l"(a), "l"(b));
}
__device__ __forceinline__ ULL dup2(float a) {
    ULL r; asm("mov.b64 %0, {%1, %1};" : "=l"(r) : "f"(a)); return r;
}
__device__ __forceinline__ float2 unpk2(ULL v) {
    float lo, hi; asm("mov.b64 {%0, %1}, %2;" : "=f"(lo), "=f"(hi) : "l"(v));
    return make_float2(lo, hi);
}
__device__ __forceinline__ float eluf(float x) { return x > 0.f ? x : expm1f(x); }

// mode 0: C = g_agg @ B + bias                       (C = d_out emb)
// mode 1: g_Z1 = elu(g_X @ g_Bm + cvec + t*wt + r*wr)
// mode 2: g_Z2 = elu(g_Z1 @ B + bias)
__global__ __launch_bounds__(256) void k_gemm(
        int mode, int M, int K,
        const float* __restrict__ Bext, float* __restrict__ Cout,
        const float* __restrict__ bias,
        const float* __restrict__ wt, const float* __restrict__ wr,
        const float* __restrict__ tv, const float* __restrict__ rv) {
    const float* A = (mode == 0) ? g_agg : (mode == 1 ? g_X : g_Z1);
    const float* B = (mode == 1) ? g_Bm : Bext;
    float*       C = (mode == 0) ? Cout : (mode == 1 ? g_Z1 : g_Z2);

    __shared__ float As[16][128];
    __shared__ float Bs[16][128];
    const int tid = threadIdx.x;
    const int m0 = blockIdx.y * 128;
    const int n0 = blockIdx.x * 128;
    const int tx = tid & 15;
    const int ty = tid >> 4;
    const int arow = tid >> 2;
    const int ak   = (tid & 3) * 4;
    const int bkr  = tid >> 5;
    const int bn   = (tid & 31) * 4;

    ULL acc[8][4];
    #pragma unroll
    for (int i = 0; i < 8; i++)
        #pragma unroll
        for (int j = 0; j < 4; j++) acc[i][j] = 0ull;

    for (int k0 = 0; k0 < K; k0 += 16) {
        #pragma unroll
        for (int h = 0; h < 2; h++) {
            int r = arow + h*64;
            float4 v = make_float4(0.f, 0.f, 0.f, 0.f);
            if (m0 + r < M) v = *(const float4*)(A + (size_t)(m0+r)*K + k0 + ak);
            As[ak+0][r] = v.x; As[ak+1][r] = v.y;
            As[ak+2][r] = v.z; As[ak+3][r] = v.w;
        }
        #pragma unroll
        for (int h = 0; h < 2; h++) {
            int kk = bkr + h*8;
            *(float4*)&Bs[kk][bn] = *(const float4*)(B + (size_t)(k0+kk)*512 + n0 + bn);
        }
        __syncthreads();
        #pragma unroll
        for (int kk = 0; kk < 16; kk++) {
            float4 a0 = *(const float4*)&As[kk][ty*8];
            float4 a1 = *(const float4*)&As[kk][ty*8+4];
            const ULL* bp = (const ULL*)&Bs[kk][tx*8];
            ULL b0 = bp[0], b1 = bp[1], b2 = bp[2], b3 = bp[3];
            float av[8] = {a0.x,a0.y,a0.z,a0.w,a1.x,a1.y,a1.z,a1.w};
            #pragma unroll
            for (int i = 0; i < 8; i++) {
                ULL ad = dup2(av[i]);
                fma2(acc[i][0], ad, b0); fma2(acc[i][1], ad, b1);
                fma2(acc[i][2], ad, b2); fma2(acc[i][3], ad, b3);
            }
        }
        __syncthreads();
    }

    #pragma unroll
    for (int i = 0; i < 8; i++) {
        int m = m0 + ty*8 + i;
        if (m >= M) continue;
        float t = 0.f, r = 0.f;
        if (mode == 1) { t = tv[m]; r = rv[m]; }
        float o[8];
        #pragma unroll
        for (int j = 0; j < 4; j++) {
            float2 v = unpk2(acc[i][j]);
            int n = n0 + tx*8 + j*2;
            if (mode == 1) {
                o[j*2]   = eluf(v.x + g_cvec[n]   + t*wt[n]   + r*wr[n]);
                o[j*2+1] = eluf(v.y + g_cvec[n+1] + t*wt[n+1] + r*wr[n+1]);
            } else {
                float a = v.x + bias[n], b = v.y + bias[n+1];
                if (mode == 2) { a = eluf(a); b = eluf(b); }
                o[j*2] = a; o[j*2+1] = b;
            }
        }
        float4* cp = (float4*)(C + (size_t)m*512 + n0 + tx*8);
        cp[0] = make_float4(o[0], o[1], o[2], o[3]);
        cp[1] = make_float4(o[4], o[5], o[6], o[7]);
    }
}

// ----------------------------- MLP prep --------------------------------------
__global__ void k_hf(const float* __restrict__ out) {
    g_hf[threadIdx.x] = out[(size_t)OFF_EMB + (size_t)NNODE*HID + threadIdx.x];
}

__global__ void k_cvec(const float* __restrict__ W1h, const float* __restrict__ bh1) {
    __shared__ float sh[HID];
    int t = threadIdx.x;
    sh[t] = g_hf[t];
    __syncthreads();
    float s = bh1[t];
    for (int k = 0; k < HID; k++) s += sh[k] * W1h[(size_t)k*512 + t];
    g_cvec[t] = s;
}

__global__ void k_buildB(const float* __restrict__ W1h) {
    int rr = blockIdx.x;   // 0..1023
    const float* srcB = W1h + (size_t)(512 + rr)*512;
    float hf = (rr < 512) ? g_hf[rr] : 0.f;
    const float* srcD = W1h + (size_t)((rr < 512) ? (1536 + rr) : (512 + rr))*512;
    for (int n = threadIdx.x; n < 512; n += blockDim.x)
        g_Bm[(size_t)rr*512 + n] = srcB[n] + hf*srcD[n];
}

__global__ void k_xef(float* __restrict__ out, const int* __restrict__ bch,
                      const float* __restrict__ tval, const float* __restrict__ isroot) {
    int u = blockIdx.x;
    int bc = bch[u];
    const float* ht = out + (size_t)OFF_EMB + (size_t)bc*512;
    float* ef = out + (size_t)OFF_EF + (size_t)u*2050;
    float* X  = g_X + (size_t)u*1024;
    for (int j = threadIdx.x; j < 512; j += blockDim.x) {
        float h = ht[j], f = g_hf[j];
        float ab = fabsf(f - h), pr = f*h;
        X[j] = h; X[512 + j] = ab;
        ef[j] = f; ef[512 + j] = h; ef[1024 + j] = ab; ef[1536 + j] = pr;
    }
    if (threadIdx.x == 0) { ef[2048] = tval[u]; ef[2049] = isroot[u]; }
}

// ----------------------------- head ------------------------------------------
__global__ void k_logits(const float* __restrict__ W3, const float* __restrict__ b3,
                         float* __restrict__ out) {
    int w = (blockIdx.x * blockDim.x + threadIdx.x) >> 5;
    int lane = threadIdx.x & 31;
    if (w >= NNODE) return;
    const float* z = g_Z2 + (size_t)w*512;
    float s = 0.f;
    #pragma unroll 4
    for (int j = lane; j < 512; j += 32) s += z[j]*W3[j];
    #pragma unroll
    for (int off = 16; off; off >>= 1) s += __shfl_down_sync(0xffffffffu, s, off);
    if (lane == 0) out[w] = s + b3[0];
}

__global__ void k_softmax(float* __restrict__ out) {
    __shared__ float red[1024];
    int tid = threadIdx.x;
    float m = -1e30f;
    for (int i = tid; i < NNODE; i += 1024) m = fmaxf(m, out[i]);
    red[tid] = m; __syncthreads();
    for (int s = 512; s; s >>= 1) {
        if (tid < s) red[tid] = fmaxf(red[tid], red[tid + s]);
        __syncthreads();
    }
    float M = red[0]; __syncthreads();
    float sum = 0.f;
    for (int i = tid; i < NNODE; i += 1024) sum += __expf(out[i] - M);
    red[tid] = sum; __syncthreads();
    for (int s = 512; s; s >>= 1) {
        if (tid < s) red[tid] += red[tid + s];
        __syncthreads();
    }
    float inv = 1.f / red[0];
    for (int i = tid; i < NNODE; i += 1024)
        out[NNODE + i] = __expf(out[i] - M) * inv;
}

// ----------------------------- launcher --------------------------------------
extern "C" void kernel_launch(void* const* d_in, const int* in_sizes, int n_in,
                              void* d_out, int out_size) {
    const int*   ns     = (const int*)d_in[0];
    const int*   ch0    = (const int*)d_in[1];
    const int*   ch1    = (const int*)d_in[2];
    const int*   parent = (const int*)d_in[3];
    const int*   neigh  = (const int*)d_in[4];
    const int*   bch    = (const int*)d_in[5];
    const int*   focal  = (const int*)d_in[6];
    const float* tv     = (const float*)d_in[7];
    const float* isroot = (const float*)d_in[8];
    const float* W1     = (const float*)d_in[9];
    const float* b1     = (const float*)d_in[10];
    const float* W2     = (const float*)d_in[11];
    const float* b2     = (const float*)d_in[12];
    const float* Wh1    = (const float*)d_in[13];
    const float* bh1    = (const float*)d_in[14];
    const float* Wh2    = (const float*)d_in[15];
    const float* bh2    = (const float*)d_in[16];
    const float* Wh3    = (const float*)d_in[17];
    const float* bh3    = (const float*)d_in[18];
    float* out = (float*)d_out;

    k_reset<<<16, 1024>>>();
    k_leafinit<<<NLEAF + 1, 128>>>(ns, focal, W1);
    k_focalfeat<<<4, 1024>>>(focal, out);
    k_tree<<<128, 256>>>(ch0, ch1, parent);
    k_agg<<<NROW, 128>>>(0, neigh, b1);
    k_agg<<<NROW, 128>>>(1, neigh, b1);

    dim3 g0(4, 64);
    k_gemm<<<g0, 256>>>(0, NROW, 512, W2, out + OFF_EMB, b2,
                        nullptr, nullptr, nullptr, nullptr);
    k_hf<<<1, 512>>>(out);
    k_cvec<<<1, 512>>>(Wh1, bh1);
    k_buildB<<<1024, 256>>>(Wh1);
    k_xef<<<NNODE, 256>>>(out, bch, tv, isroot);
    k_gemm<<<g0, 256>>>(1, NNODE, 1024, nullptr, nullptr, nullptr,
                        Wh1 + (size_t)2048*512, Wh1 + (size_t)2049*512, tv, isroot);
    k_gemm<<<g0, 256>>>(2, NNODE, 512, Wh2, nullptr, bh2,
                        nullptr, nullptr, nullptr, nullptr);
    k_logits<<<256, 1024>>>(Wh3, bh3, out);
    k_softmax<<<1, 1024>>>(out);
}

// round 3
// speedup vs baseline: 1.0417x; 1.0417x over previous
#include <cuda_runtime.h>

#define NLEAF 4096
#define NNODE 8191
#define NROW  8192
#define HID   512

#define OFF_EF     16382
#define OFF_EMB    16807932
#define OFF_FOCAL  21002236

typedef unsigned long long ULL;

// ----------------------------- scratch ---------------------------------------
__device__ float g_dW[NROW*HID];
__device__ float g_h[NROW*HID];
__device__ float g_agg[NROW*HID];
__device__ float g_X[(size_t)NNODE*1024];
__device__ float g_Z1[NNODE*HID];
__device__ float g_Z2[NNODE*HID];
__device__ float g_Bm[1024*HID];
__device__ float g_cvec[HID];
__device__ float g_hf[HID];
__device__ float g_c[NNODE];          // zero-init; leaves stay 0 forever
__device__ int   g_postF[NNODE];
__device__ int   g_preF[NNODE];

// ----------------------------- sync helpers ----------------------------------
__device__ __forceinline__ void st_rel(int* p, int v) {
    asm volatile("st.release.gpu.global.b32 [%0], %1;" :: "l"(p), "r"(v) : "memory");
}
__device__ __forceinline__ int ld_acq(const int* p) {
    int v;
    asm volatile("ld.acquire.gpu.global.b32 %0, [%1];" : "=r"(v) : "l"(p) : "memory");
    return v;
}

// ----------------------------- small kernels ---------------------------------
__global__ void k_reset(const int* __restrict__ focal, float* __restrict__ out) {
    int i = blockIdx.x * blockDim.x + threadIdx.x;
    if (i < NNODE) g_postF[i] = 0;
    else if (i < 2*NNODE) g_preF[i - NNODE] = 0;
    if (i < NLEAF) out[OFF_FOCAL + i] = (i == focal[0]) ? 1.f : 0.f;
}

__global__ void k_leafinit(const int* __restrict__ ns, const int* __restrict__ focal,
                           const float* __restrict__ W1) {
    int b = blockIdx.x;                 // 0..NLEAF (last = focal row)
    int u, src;
    if (b == NLEAF) { u = NNODE; src = focal[0]; }
    else            { u = b; src = ns[b]; if (src < 0) return; }
    const float4* w = (const float4*)(W1 + (size_t)src*HID);
    float4* d = (float4*)(g_dW + (size_t)u*HID);
    d[threadIdx.x] = w[threadIdx.x];    // 128 threads * float4
}

// ----------------------------- tree recursion --------------------------------
// one warp per internal node; flags chased via acquire/release
__global__ void k_tree(const int* __restrict__ ch0, const int* __restrict__ ch1,
                       const int* __restrict__ parent) {
    const int w    = blockIdx.x * (blockDim.x >> 5) + (threadIdx.x >> 5);
    const int lane = threadIdx.x & 31;
    const int NI   = NNODE - NLEAF;     // 4095
    const int root = NNODE - 1;
    if (w >= NI) return;
    const int u = NLEAF + w;
    const int a = ch0[u], b = ch1[u];

    // -------- postorder --------
    if (a >= NLEAF) while (!ld_acq(&g_postF[a])) __nanosleep(32);
    if (b >= NLEAF) while (!ld_acq(&g_postF[b])) __nanosleep(32);
    __syncwarp();
    float ca = __ldcg(&g_c[a]);
    float cb = __ldcg(&g_c[b]);
    float cu = 1.f / (3.f - ca - cb);
    const float4* pa = (const float4*)(g_dW + (size_t)a*HID);
    const float4* pb = (const float4*)(g_dW + (size_t)b*HID);
    float4*       pu = (float4*)(g_dW + (size_t)u*HID);
    #pragma unroll
    for (int j = 0; j < 4; j++) {
        int c4 = lane + j*32;
        float4 x = __ldcg(pa + c4), y = __ldcg(pb + c4), r;
        r.x = cu*(x.x+y.x); r.y = cu*(x.y+y.y);
        r.z = cu*(x.z+y.z); r.w = cu*(x.w+y.w);
        pu[c4] = r;
    }
    if (lane == 0) g_c[u] = cu;
    __threadfence();
    __syncwarp();
    if (lane == 0) {
        st_rel(&g_postF[u], 1);
        if (u == root) st_rel(&g_preF[u], 1);   // root: final = post value
    }
    __syncwarp();
    if (u == root) return;

    // -------- preorder --------
    const int p = parent[u];
    while (!ld_acq(&g_preF[p])) __nanosleep(32);
    __syncwarp();
    const float4* pp = (const float4*)(g_dW + (size_t)p*HID);
    #pragma unroll
    for (int j = 0; j < 4; j++) {
        int c4 = lane + j*32;
        float4 x = __ldcg(pp + c4);
        float4 r = pu[c4];
        r.x += cu*x.x; r.y += cu*x.y; r.z += cu*x.z; r.w += cu*x.w;
        pu[c4] = r;
    }
    __threadfence();
    __syncwarp();
    if (lane == 0) st_rel(&g_preF[u], 1);
}

// ----------------------------- GCN aggregation -------------------------------
__global__ void k_agg(int phase, const int* __restrict__ neigh,
                      const float* __restrict__ bias) {
    const float* src = (phase == 0) ? g_dW : g_h;
    float*       dst = (phase == 0) ? g_h  : g_agg;
    int u = blockIdx.x;
    int n0 = neigh[3*u], n1 = neigh[3*u+1], n2 = neigh[3*u+2];
    float inv = 1.f / (1.f + (n0 >= 0) + (n1 >= 0) + (n2 >= 0));
    const float4* s  = (const float4*)(src + (size_t)u*HID);
    const float4* p0 = (const float4*)(src + (size_t)(n0 >= 0 ? n0 : 0)*HID);
    const float4* p1 = (const float4*)(src + (size_t)(n1 >= 0 ? n1 : 0)*HID);
    const float4* p2 = (const float4*)(src + (size_t)(n2 >= 0 ? n2 : 0)*HID);
    float4* d = (float4*)(dst + (size_t)u*HID);
    int j = threadIdx.x;                  // 128 threads
    float4 v = s[j];
    if (n0 >= 0) { float4 t = p0[j]; v.x += t.x; v.y += t.y; v.z += t.z; v.w += t.w; }
    if (n1 >= 0) { float4 t = p1[j]; v.x += t.x; v.y += t.y; v.z += t.z; v.w += t.w; }
    if (n2 >= 0) { float4 t = p2[j]; v.x += t.x; v.y += t.y; v.z += t.z; v.w += t.w; }
    v.x *= inv; v.y *= inv; v.z *= inv; v.w *= inv;
    if (phase == 0) {
        float4 b = ((const float4*)bias)[j];
        v.x = fmaxf(v.x + b.x, 0.f); v.y = fmaxf(v.y + b.y, 0.f);
        v.z = fmaxf(v.z + b.z, 0.f); v.w = fmaxf(v.w + b.w, 0.f);
    }
    d[j] = v;
}

// ----------------------------- f32x2 SGEMM -----------------------------------
__device__ __forceinline__ void fma2(ULL &d, ULL a, ULL b) {
    asm("fma.rn.f32x2 %0, %1, %2, %0;" : "+l"(d) : "l"(a), "l"(b));
}
__device__ __forceinline__ float2 unpk2(ULL v) {
    float lo, hi; asm("mov.b64 {%0, %1}, %2;" : "=f"(lo), "=f"(hi) : "l"(v));
    return make_float2(lo, hi);
}
__device__ __forceinline__ float eluf(float x) { return x > 0.f ? x : expm1f(x); }

// mode 0: C = g_agg @ B + bias                       (C = d_out emb region)
// mode 1: g_Z1 = elu(g_X @ g_Bm + cvec + t*wt + r*wr)
// mode 2: g_Z2 = elu(g_Z1 @ B + bias)
// 128x128x16 tile, 256 threads, acc packed over N via f32x2; A duplicated in smem.
__global__ __launch_bounds__(256, 2) void k_gemm(
        int mode, int M, int K,
        const float* __restrict__ Bext, float* __restrict__ Cout,
        const float* __restrict__ bias,
        const float* __restrict__ wt, const float* __restrict__ wr,
        const float* __restrict__ tv, const float* __restrict__ rv) {
    const float* A = (mode == 0) ? g_agg : (mode == 1 ? g_X : g_Z1);
    const float* B = (mode == 1) ? g_Bm : Bext;
    float*       C = (mode == 0) ? Cout : (mode == 1 ? g_Z1 : g_Z2);

    __shared__ float As2[16][260];   // duplicated pairs: As2[k][2m]=As2[k][2m+1]=A
    __shared__ float Bs[16][132];

    const int tid = threadIdx.x;
    const int m0 = blockIdx.y * 128;
    const int n0 = blockIdx.x * 128;
    const int tx = tid & 15;
    const int ty = tid >> 4;

    const int ar = tid >> 2;          // A fill row 0..63 (+64)
    const int ak = (tid & 3) * 4;     // A fill k group
    const int br = tid >> 5;          // B fill row 0..7 (+8)
    const int bc = (tid & 31) * 4;    // B fill col group

    ULL acc[8][4];
    #pragma unroll
    for (int i = 0; i < 8; i++)
        #pragma unroll
        for (int j = 0; j < 4; j++) acc[i][j] = 0ull;

    const float4 z4 = make_float4(0.f, 0.f, 0.f, 0.f);
    float4 a0, a1, b0, b1;
    // preload tile k0=0
    a0 = (m0 + ar      < M) ? *(const float4*)(A + (size_t)(m0+ar   )*K + ak) : z4;
    a1 = (m0 + ar + 64 < M) ? *(const float4*)(A + (size_t)(m0+ar+64)*K + ak) : z4;
    b0 = *(const float4*)(B + (size_t)(br    )*512 + n0 + bc);
    b1 = *(const float4*)(B + (size_t)(br + 8)*512 + n0 + bc);

    for (int k0 = 0; k0 < K; k0 += 16) {
        // stage regs -> smem (A duplicated)
        As2[ak+0][2*ar] = a0.x; As2[ak+0][2*ar+1] = a0.x;
        As2[ak+1][2*ar] = a0.y; As2[ak+1][2*ar+1] = a0.y;
        As2[ak+2][2*ar] = a0.z; As2[ak+2][2*ar+1] = a0.z;
        As2[ak+3][2*ar] = a0.w; As2[ak+3][2*ar+1] = a0.w;
        As2[ak+0][2*(ar+64)] = a1.x; As2[ak+0][2*(ar+64)+1] = a1.x;
        As2[ak+1][2*(ar+64)] = a1.y; As2[ak+1][2*(ar+64)+1] = a1.y;
        As2[ak+2][2*(ar+64)] = a1.z; As2[ak+2][2*(ar+64)+1] = a1.z;
        As2[ak+3][2*(ar+64)] = a1.w; As2[ak+3][2*(ar+64)+1] = a1.w;
        *(float4*)&Bs[br    ][bc] = b0;
        *(float4*)&Bs[br + 8][bc] = b1;
        __syncthreads();
        int kn = k0 + 16;
        if (kn < K) {
            a0 = (m0 + ar      < M) ? *(const float4*)(A + (size_t)(m0+ar   )*K + kn + ak) : z4;
            a1 = (m0 + ar + 64 < M) ? *(const float4*)(A + (size_t)(m0+ar+64)*K + kn + ak) : z4;
            b0 = *(const float4*)(B + (size_t)(kn+br    )*512 + n0 + bc);
            b1 = *(const float4*)(B + (size_t)(kn+br + 8)*512 + n0 + bc);
        }
        #pragma unroll
        for (int kk = 0; kk < 16; kk++) {
            const ulonglong2* ap = (const ulonglong2*)&As2[kk][ty*16];
            ulonglong2 A01 = ap[0], A23 = ap[1], A45 = ap[2], A67 = ap[3];
            ULL bb0 = *(const ULL*)&Bs[kk][2*tx];
            ULL bb1 = *(const ULL*)&Bs[kk][2*tx + 32];
            ULL bb2 = *(const ULL*)&Bs[kk][2*tx + 64];
            ULL bb3 = *(const ULL*)&Bs[kk][2*tx + 96];
            ULL am[8] = {A01.x, A01.y, A23.x, A23.y, A45.x, A45.y, A67.x, A67.y};
            #pragma unroll
            for (int i = 0; i < 8; i++) {
                fma2(acc[i][0], am[i], bb0);
                fma2(acc[i][1], am[i], bb1);
                fma2(acc[i][2], am[i], bb2);
                fma2(acc[i][3], am[i], bb3);
            }
        }
        __syncthreads();
    }

    #pragma unroll
    for (int i = 0; i < 8; i++) {
        int m = m0 + ty*8 + i;
        if (m >= M) continue;
        float t = 0.f, r = 0.f;
        if (mode == 1) { t = tv[m]; r = rv[m]; }
        #pragma unroll
        for (int j = 0; j < 4; j++) {
            int n = n0 + 2*tx + 32*j;
            float2 v = unpk2(acc[i][j]);
            float o0, o1;
            if (mode == 1) {
                float2 cv = *(const float2*)&g_cvec[n];
                float2 wtv = *(const float2*)&wt[n];
                float2 wrv = *(const float2*)&wr[n];
                o0 = eluf(v.x + cv.x + t*wtv.x + r*wrv.x);
                o1 = eluf(v.y + cv.y + t*wtv.y + r*wrv.y);
            } else {
                float2 bv = *(const float2*)&bias[n];
                o0 = v.x + bv.x; o1 = v.y + bv.y;
                if (mode == 2) { o0 = eluf(o0); o1 = eluf(o1); }
            }
            *(float2*)(C + (size_t)m*512 + n) = make_float2(o0, o1);
        }
    }
}

// ----------------------------- MLP prep --------------------------------------
__global__ void k_hf(const float* __restrict__ out) {
    g_hf[threadIdx.x] = out[(size_t)OFF_EMB + (size_t)NNODE*HID + threadIdx.x];
}

__global__ void k_cvec(const float* __restrict__ W1h, const float* __restrict__ bh1) {
    __shared__ float sh[HID];
    int t = threadIdx.x;
    sh[t] = g_hf[t];
    __syncthreads();
    float s = bh1[t];
    for (int k = 0; k < HID; k++) s += sh[k] * W1h[(size_t)k*512 + t];
    g_cvec[t] = s;
}

__global__ void k_buildB(const float* __restrict__ W1h) {
    int rr = blockIdx.x;   // 0..1023
    const float* srcB = W1h + (size_t)(512 + rr)*512;
    float hf = (rr < 512) ? g_hf[rr] : 0.f;
    const float* srcD = W1h + (size_t)((rr < 512) ? (1536 + rr) : (512 + rr))*512;
    for (int n = threadIdx.x; n < 512; n += blockDim.x)
        g_Bm[(size_t)rr*512 + n] = srcB[n] + hf*srcD[n];
}

__global__ void k_xef(float* __restrict__ out, const int* __restrict__ bch,
                      const float* __restrict__ tval, const float* __restrict__ isroot) {
    int u = blockIdx.x;
    int bc = bch[u];
    const float* ht = out + (size_t)OFF_EMB + (size_t)bc*512;
    float* ef = out + (size_t)OFF_EF + (size_t)u*2050;
    float* X  = g_X + (size_t)u*1024;
    for (int j = threadIdx.x; j < 512; j += blockDim.x) {
        float h = ht[j], f = g_hf[j];
        float ab = fabsf(f - h), pr = f*h;
        X[j] = h; X[512 + j] = ab;
        ef[j] = f; ef[512 + j] = h; ef[1024 + j] = ab; ef[1536 + j] = pr;
    }
    if (threadIdx.x == 0) { ef[2048] = tval[u]; ef[2049] = isroot[u]; }
}

// ----------------------------- head ------------------------------------------
__global__ void k_logits(const float* __restrict__ W3, const float* __restrict__ b3,
                         float* __restrict__ out) {
    int w = (blockIdx.x * blockDim.x + threadIdx.x) >> 5;
    int lane = threadIdx.x & 31;
    if (w >= NNODE) return;
    const float* z = g_Z2 + (size_t)w*512;
    float s = 0.f;
    #pragma unroll 4
    for (int j = lane; j < 512; j += 32) s += z[j]*W3[j];
    #pragma unroll
    for (int off = 16; off; off >>= 1) s += __shfl_down_sync(0xffffffffu, s, off);
    if (lane == 0) out[w] = s + b3[0];
}

__global__ void k_softmax(float* __restrict__ out) {
    __shared__ float red[1024];
    int tid = threadIdx.x;
    float m = -1e30f;
    for (int i = tid; i < NNODE; i += 1024) m = fmaxf(m, out[i]);
    red[tid] = m; __syncthreads();
    for (int s = 512; s; s >>= 1) {
        if (tid < s) red[tid] = fmaxf(red[tid], red[tid + s]);
        __syncthreads();
    }
    float M = red[0]; __syncthreads();
    float sum = 0.f;
    for (int i = tid; i < NNODE; i += 1024) sum += __expf(out[i] - M);
    red[tid] = sum; __syncthreads();
    for (int s = 512; s; s >>= 1) {
        if (tid < s) red[tid] += red[tid + s];
        __syncthreads();
    }
    float inv = 1.f / red[0];
    for (int i = tid; i < NNODE; i += 1024)
        out[NNODE + i] = __expf(out[i] - M) * inv;
}

// ----------------------------- launcher --------------------------------------
extern "C" void kernel_launch(void* const* d_in, const int* in_sizes, int n_in,
                              void* d_out, int out_size) {
    const int*   ns     = (const int*)d_in[0];
    const int*   ch0    = (const int*)d_in[1];
    const int*   ch1    = (const int*)d_in[2];
    const int*   parent = (const int*)d_in[3];
    const int*   neigh  = (const int*)d_in[4];
    const int*   bch    = (const int*)d_in[5];
    const int*   focal  = (const int*)d_in[6];
    const float* tv     = (const float*)d_in[7];
    const float* isroot = (const float*)d_in[8];
    const float* W1     = (const float*)d_in[9];
    const float* b1     = (const float*)d_in[10];
    const float* W2     = (const float*)d_in[11];
    const float* b2     = (const float*)d_in[12];
    const float* Wh1    = (const float*)d_in[13];
    const float* bh1    = (const float*)d_in[14];
    const float* Wh2    = (const float*)d_in[15];
    const float* bh2    = (const float*)d_in[16];
    const float* Wh3    = (const float*)d_in[17];
    const float* bh3    = (const float*)d_in[18];
    float* out = (float*)d_out;

    k_reset<<<16, 1024>>>(focal, out);
    k_leafinit<<<NLEAF + 1, 128>>>(ns, focal, W1);
    k_tree<<<512, 256>>>(ch0, ch1, parent);      // one warp per internal node
    k_agg<<<NROW, 128>>>(0, neigh, b1);
    k_agg<<<NROW, 128>>>(1, neigh, b1);

    dim3 g0(4, 64);
    k_gemm<<<g0, 256>>>(0, NROW, 512, W2, out + OFF_EMB, b2,
                        nullptr, nullptr, nullptr, nullptr);
    k_hf<<<1, 512>>>(out);
    k_cvec<<<1, 512>>>(Wh1, bh1);
    k_buildB<<<1024, 256>>>(Wh1);
    k_xef<<<NNODE, 256>>>(out, bch, tv, isroot);
    k_gemm<<<g0, 256>>>(1, NNODE, 1024, nullptr, nullptr, nullptr,
                        Wh1 + (size_t)2048*512, Wh1 + (size_t)2049*512, tv, isroot);
    k_gemm<<<g0, 256>>>(2, NNODE, 512, Wh2, nullptr, bh2,
                        nullptr, nullptr, nullptr, nullptr);
    k_logits<<<256, 1024>>>(Wh3, bh3, out);
    k_softmax<<<1, 1024>>>(out);
}

// round 7
// speedup vs baseline: 1.5073x; 1.4470x over previous
#include <cuda_runtime.h>
#include <cuda_bf16.h>
#include <cstdint>

#define NLEAF 4096
#define NNODE 8191
#define NROW  8192
#define HID   512

#define OFF_EF     16382
#define OFF_EMB    16807932
#define OFF_FOCAL  21002236

typedef unsigned long long ULL;

// ----------------------------- scratch ---------------------------------------
__device__ float g_dW[NROW*HID];
__device__ float g_h[NROW*HID];
__device__ float g_Bm[1024*HID];
__device__ float g_Z2[NROW*HID];
__device__ float g_cvec[HID];
__device__ float g_hf[HID];
__device__ float g_c[NNODE];
__device__ int   g_postF[NNODE];
__device__ int   g_preF[NNODE];

// bf16 split operand buffers (k-contiguous)
__device__ __nv_bfloat16 gA_hi[(size_t)NROW*1024];
__device__ __nv_bfloat16 gA_lo[(size_t)NROW*1024];
__device__ __nv_bfloat16 gZ_hi[(size_t)NROW*512];
__device__ __nv_bfloat16 gZ_lo[(size_t)NROW*512];
__device__ __nv_bfloat16 gB_hi[(size_t)512*1024];   // [n][k]
__device__ __nv_bfloat16 gB_lo[(size_t)512*1024];

// ----------------------------- helpers ----------------------------------------
__device__ __forceinline__ void st_rel(int* p, int v) {
    asm volatile("st.release.gpu.global.b32 [%0], %1;" :: "l"(p), "r"(v) : "memory");
}
__device__ __forceinline__ int ld_acq(const int* p) {
    int v;
    asm volatile("ld.acquire.gpu.global.b32 %0, [%1];" : "=r"(v) : "l"(p) : "memory");
    return v;
}
__device__ __forceinline__ void split_bf(float v, __nv_bfloat16 &h, __nv_bfloat16 &l) {
    h = __float2bfloat16(v);
    l = __float2bfloat16(v - __bfloat162float(h));
}
__device__ __forceinline__ float eluf(float x) { return x > 0.f ? x : expm1f(x); }

__device__ __forceinline__ void mma_bf16(float* d, const uint32_t* a, uint32_t b0, uint32_t b1) {
    asm volatile(
        "mma.sync.aligned.m16n8k16.row.col.f32.bf16.bf16.f32 "
        "{%0,%1,%2,%3}, {%4,%5,%6,%7}, {%8,%9}, {%0,%1,%2,%3};"
        : "+f"(d[0]), "+f"(d[1]), "+f"(d[2]), "+f"(d[3])
        : "r"(a[0]), "r"(a[1]), "r"(a[2]), "r"(a[3]), "r"(b0), "r"(b1));
}

// ----------------------------- small kernels ---------------------------------
__global__ void k_reset(const int* __restrict__ focal, float* __restrict__ out) {
    int i = blockIdx.x * blockDim.x + threadIdx.x;
    if (i < NNODE) g_postF[i] = 0;
    else if (i < 2*NNODE) g_preF[i - NNODE] = 0;
    if (i < NLEAF) out[OFF_FOCAL + i] = (i == focal[0]) ? 1.f : 0.f;
}

__global__ void k_leafinit(const int* __restrict__ ns, const int* __restrict__ focal,
                           const float* __restrict__ W1) {
    int b = blockIdx.x;
    int u, src;
    if (b == NLEAF) { u = NNODE; src = focal[0]; }
    else            { u = b; src = ns[b]; if (src < 0) return; }
    const float4* w = (const float4*)(W1 + (size_t)src*HID);
    float4* d = (float4*)(g_dW + (size_t)u*HID);
    d[threadIdx.x] = w[threadIdx.x];
}

// ----------------------------- tree recursion --------------------------------
__global__ void k_tree(const int* __restrict__ ch0, const int* __restrict__ ch1,
                       const int* __restrict__ parent) {
    const int w    = blockIdx.x * (blockDim.x >> 5) + (threadIdx.x >> 5);
    const int lane = threadIdx.x & 31;
    const int NI   = NNODE - NLEAF;
    const int root = NNODE - 1;
    if (w >= NI) return;
    const int u = NLEAF + w;
    const int a = ch0[u], b = ch1[u];

    if (a >= NLEAF) while (!ld_acq(&g_postF[a])) __nanosleep(32);
    if (b >= NLEAF) while (!ld_acq(&g_postF[b])) __nanosleep(32);
    __syncwarp();
    float ca = __ldcg(&g_c[a]);
    float cb = __ldcg(&g_c[b]);
    float cu = 1.f / (3.f - ca - cb);
    const float4* pa = (const float4*)(g_dW + (size_t)a*HID);
    const float4* pb = (const float4*)(g_dW + (size_t)b*HID);
    float4*       pu = (float4*)(g_dW + (size_t)u*HID);
    #pragma unroll
    for (int j = 0; j < 4; j++) {
        int c4 = lane + j*32;
        float4 x = __ldcg(pa + c4), y = __ldcg(pb + c4), r;
        r.x = cu*(x.x+y.x); r.y = cu*(x.y+y.y);
        r.z = cu*(x.z+y.z); r.w = cu*(x.w+y.w);
        pu[c4] = r;
    }
    if (lane == 0) g_c[u] = cu;
    __threadfence();
    __syncwarp();
    if (lane == 0) {
        st_rel(&g_postF[u], 1);
        if (u == root) st_rel(&g_preF[u], 1);
    }
    __syncwarp();
    if (u == root) return;

    const int p = parent[u];
    while (!ld_acq(&g_preF[p])) __nanosleep(32);
    __syncwarp();
    const float4* pp = (const float4*)(g_dW + (size_t)p*HID);
    #pragma unroll
    for (int j = 0; j < 4; j++) {
        int c4 = lane + j*32;
        float4 x = __ldcg(pp + c4);
        float4 r = pu[c4];
        r.x += cu*x.x; r.y += cu*x.y; r.z += cu*x.z; r.w += cu*x.w;
        pu[c4] = r;
    }
    __threadfence();
    __syncwarp();
    if (lane == 0) st_rel(&g_preF[u], 1);
}

// ----------------------------- GCN aggregation -------------------------------
__global__ void k_agg(int phase, const int* __restrict__ neigh,
                      const float* __restrict__ bias) {
    const float* src = (phase == 0) ? g_dW : g_h;
    int u = blockIdx.x;
    int n0 = neigh[3*u], n1 = neigh[3*u+1], n2 = neigh[3*u+2];
    float inv = 1.f / (1.f + (n0 >= 0) + (n1 >= 0) + (n2 >= 0));
    const float4* s  = (const float4*)(src + (size_t)u*HID);
    const float4* p0 = (const float4*)(src + (size_t)(n0 >= 0 ? n0 : 0)*HID);
    const float4* p1 = (const float4*)(src + (size_t)(n1 >= 0 ? n1 : 0)*HID);
    const float4* p2 = (const float4*)(src + (size_t)(n2 >= 0 ? n2 : 0)*HID);
    int j = threadIdx.x;
    float4 v = s[j];
    if (n0 >= 0) { float4 t = p0[j]; v.x += t.x; v.y += t.y; v.z += t.z; v.w += t.w; }
    if (n1 >= 0) { float4 t = p1[j]; v.x += t.x; v.y += t.y; v.z += t.z; v.w += t.w; }
    if (n2 >= 0) { float4 t = p2[j]; v.x += t.x; v.y += t.y; v.z += t.z; v.w += t.w; }
    v.x *= inv; v.y *= inv; v.z *= inv; v.w *= inv;
    if (phase == 0) {
        float4 b = ((const float4*)bias)[j];
        v.x = fmaxf(v.x + b.x, 0.f); v.y = fmaxf(v.y + b.y, 0.f);
        v.z = fmaxf(v.z + b.z, 0.f); v.w = fmaxf(v.w + b.w, 0.f);
        ((float4*)(g_h + (size_t)u*HID))[j] = v;
    } else {
        __nv_bfloat16 h0,l0,h1,l1,h2,l2,h3,l3;
        split_bf(v.x, h0, l0); split_bf(v.y, h1, l1);
        split_bf(v.z, h2, l2); split_bf(v.w, h3, l3);
        ushort4 sh = { __bfloat16_as_ushort(h0), __bfloat16_as_ushort(h1),
                       __bfloat16_as_ushort(h2), __bfloat16_as_ushort(h3) };
        ushort4 sl = { __bfloat16_as_ushort(l0), __bfloat16_as_ushort(l1),
                       __bfloat16_as_ushort(l2), __bfloat16_as_ushort(l3) };
        *(ushort4*)(gA_hi + (size_t)u*1024 + 4*j) = sh;
        *(ushort4*)(gA_lo + (size_t)u*1024 + 4*j) = sl;
    }
}

// ----------------------------- B split (+transpose) ---------------------------
// useBm: read from device-global g_Bm (NOT passable as a host arg) else from W.
__global__ void k_splitB(const float* __restrict__ W, int K, int useBm) {
    const float* src = useBm ? g_Bm : W;
    int n = blockIdx.x;
    for (int k = threadIdx.x; k < K; k += blockDim.x) {
        float v = src[(size_t)k*512 + n];
        __nv_bfloat16 h, l; split_bf(v, h, l);
        gB_hi[(size_t)n*1024 + k] = h;
        gB_lo[(size_t)n*1024 + k] = l;
    }
}

// ----------------------------- mma.sync bf16x3 GEMM ---------------------------
// A selected INSIDE the kernel (device symbols are not valid host-side args):
// mode 0: A=gA_hi/lo stride 1024, K=512 ; Cout = D + bias (fp32)
// mode 1: A=gA_hi/lo stride 1024, K=1024; gZ_hi/lo = split(elu(D + cvec + t*wt + r*wr))
// mode 2: A=gZ_hi/lo stride 512,  K=512 ; g_Z2 = elu(D + bias)
#define SROW 40   // smem row stride in bf16 (80B)
__global__ __launch_bounds__(256) void k_mma(
        int mode, int M, int K,
        const float* __restrict__ bias,
        const float* __restrict__ wt, const float* __restrict__ wr,
        const float* __restrict__ tv, const float* __restrict__ rv,
        float* __restrict__ Cout) {
    const __nv_bfloat16* Ahi = (mode == 2) ? gZ_hi : gA_hi;
    const __nv_bfloat16* Alo = (mode == 2) ? gZ_lo : gA_lo;
    const int strideA = (mode == 2) ? 512 : 1024;

    __shared__ __align__(16) __nv_bfloat16 sm[4*128*SROW];   // 40960 B: Ah, Al, Bh, Bl
    const int tid  = threadIdx.x;
    const int wid  = tid >> 5;
    const int lane = tid & 31;
    const int gid  = lane >> 2;       // 0..7
    const int tig  = lane & 3;        // 0..3
    const int m0 = blockIdx.y * 128;
    const int n0 = blockIdx.x * 128;
    const int wm = (wid & 3) * 32;    // warp m offset
    const int wn = (wid >> 2) * 64;   // warp n offset
    const int Cn = K >> 5;            // 32-wide K chunks

    float acc[2][8][4];
    #pragma unroll
    for (int i = 0; i < 2; i++)
        #pragma unroll
        for (int j = 0; j < 8; j++)
            #pragma unroll
            for (int q = 0; q < 4; q++) acc[i][j][q] = 0.f;

    uint4 rAh[2], rAl[2], rBh[2], rBl[2];
    auto load_g = [&](int c) {
        const size_t kb = (size_t)c * 32;
        #pragma unroll
        for (int it = 0; it < 2; it++) {
            int idx = it*256 + tid;
            int row = idx >> 2, seg = idx & 3;
            rAh[it] = *(const uint4*)(Ahi + (size_t)(m0+row)*strideA + kb + seg*8);
            rAl[it] = *(const uint4*)(Alo + (size_t)(m0+row)*strideA + kb + seg*8);
            rBh[it] = *(const uint4*)(gB_hi + (size_t)(n0+row)*1024 + kb + seg*8);
            rBl[it] = *(const uint4*)(gB_lo + (size_t)(n0+row)*1024 + kb + seg*8);
        }
    };
    auto store_s = [&]() {
        #pragma unroll
        for (int it = 0; it < 2; it++) {
            int idx = it*256 + tid;
            int row = idx >> 2, seg = idx & 3;
            int so = row*SROW + seg*8;
            *(uint4*)(sm + 0*128*SROW + so) = rAh[it];
            *(uint4*)(sm + 1*128*SROW + so) = rAl[it];
            *(uint4*)(sm + 2*128*SROW + so) = rBh[it];
            *(uint4*)(sm + 3*128*SROW + so) = rBl[it];
        }
    };

    load_g(0);
    for (int c = 0; c < Cn; c++) {
        store_s();
        __syncthreads();
        if (c + 1 < Cn) load_g(c + 1);     // global->reg prefetch overlaps compute
        const __nv_bfloat16* sAh = sm;
        const __nv_bfloat16* sAl = sm + 128*SROW;
        const __nv_bfloat16* sBh = sm + 2*128*SROW;
        const __nv_bfloat16* sBl = sm + 3*128*SROW;
        #pragma unroll
        for (int ks = 0; ks < 32; ks += 16) {
            uint32_t aH[2][4], aL[2][4];
            #pragma unroll
            for (int i = 0; i < 2; i++) {
                int rb = wm + i*16 + gid;
                int cb = ks + tig*2;
                aH[i][0] = *(const uint32_t*)(sAh + rb*SROW + cb);
                aH[i][1] = *(const uint32_t*)(sAh + (rb+8)*SROW + cb);
                aH[i][2] = *(const uint32_t*)(sAh + rb*SROW + cb + 8);
                aH[i][3] = *(const uint32_t*)(sAh + (rb+8)*SROW + cb + 8);
                aL[i][0] = *(const uint32_t*)(sAl + rb*SROW + cb);
                aL[i][1] = *(const uint32_t*)(sAl + (rb+8)*SROW + cb);
                aL[i][2] = *(const uint32_t*)(sAl + rb*SROW + cb + 8);
                aL[i][3] = *(const uint32_t*)(sAl + (rb+8)*SROW + cb + 8);
            }
            #pragma unroll
            for (int j = 0; j < 8; j++) {
                int nb = wn + j*8 + gid;
                int cb = ks + tig*2;
                uint32_t bh0 = *(const uint32_t*)(sBh + nb*SROW + cb);
                uint32_t bh1 = *(const uint32_t*)(sBh + nb*SROW + cb + 8);
                uint32_t bl0 = *(const uint32_t*)(sBl + nb*SROW + cb);
                uint32_t bl1 = *(const uint32_t*)(sBl + nb*SROW + cb + 8);
                #pragma unroll
                for (int i = 0; i < 2; i++) {
                    mma_bf16(acc[i][j], aH[i], bh0, bh1);
                    mma_bf16(acc[i][j], aH[i], bl0, bl1);
                    mma_bf16(acc[i][j], aL[i], bh0, bh1);
                }
            }
        }
        __syncthreads();
    }

    // ----- epilogue -----
    #pragma unroll
    for (int i = 0; i < 2; i++) {
        #pragma unroll
        for (int r2 = 0; r2 < 2; r2++) {
            int m = m0 + wm + i*16 + gid + r2*8;
            if (m >= M) continue;
            float t = 0.f, r = 0.f;
            if (mode == 1) { t = tv[m]; r = rv[m]; }
            #pragma unroll
            for (int j = 0; j < 8; j++) {
                int n = n0 + wn + j*8 + tig*2;
                float v0 = acc[i][j][r2*2 + 0];
                float v1 = acc[i][j][r2*2 + 1];
                if (mode == 0) {
                    float2 bv = *(const float2*)&bias[n];
                    *(float2*)(Cout + (size_t)m*512 + n) = make_float2(v0 + bv.x, v1 + bv.y);
                } else if (mode == 1) {
                    float2 cv = *(const float2*)&g_cvec[n];
                    float2 wtv = *(const float2*)&wt[n];
                    float2 wrv = *(const float2*)&wr[n];
                    float z0 = eluf(v0 + cv.x + t*wtv.x + r*wrv.x);
                    float z1 = eluf(v1 + cv.y + t*wtv.y + r*wrv.y);
                    __nv_bfloat16 h0, l0, h1, l1;
                    split_bf(z0, h0, l0); split_bf(z1, h1, l1);
                    ushort2 sh = { __bfloat16_as_ushort(h0), __bfloat16_as_ushort(h1) };
                    ushort2 sl = { __bfloat16_as_ushort(l0), __bfloat16_as_ushort(l1) };
                    *(ushort2*)(gZ_hi + (size_t)m*512 + n) = sh;
                    *(ushort2*)(gZ_lo + (size_t)m*512 + n) = sl;
                } else {
                    float2 bv = *(const float2*)&bias[n];
                    *(float2*)(g_Z2 + (size_t)m*512 + n) =
                        make_float2(eluf(v0 + bv.x), eluf(v1 + bv.y));
                }
            }
        }
    }
}

// ----------------------------- MLP prep --------------------------------------
__global__ void k_hf(const float* __restrict__ out) {
    g_hf[threadIdx.x] = out[(size_t)OFF_EMB + (size_t)NNODE*HID + threadIdx.x];
}

__global__ void k_cvec(const float* __restrict__ W1h, const float* __restrict__ bh1) {
    __shared__ float sh[HID];
    int t = threadIdx.x;
    sh[t] = g_hf[t];
    __syncthreads();
    float s = bh1[t];
    for (int k = 0; k < HID; k++) s += sh[k] * W1h[(size_t)k*512 + t];
    g_cvec[t] = s;
}

__global__ void k_buildB(const float* __restrict__ W1h) {
    int rr = blockIdx.x;   // 0..1023
    const float* srcB = W1h + (size_t)(512 + rr)*512;
    float hf = (rr < 512) ? g_hf[rr] : 0.f;
    const float* srcD = W1h + (size_t)((rr < 512) ? (1536 + rr) : (512 + rr))*512;
    for (int n = threadIdx.x; n < 512; n += blockDim.x)
        g_Bm[(size_t)rr*512 + n] = srcB[n] + hf*srcD[n];
}

__global__ void k_xef(float* __restrict__ out, const int* __restrict__ bch,
                      const float* __restrict__ tval, const float* __restrict__ isroot) {
    int u = blockIdx.x;
    int bc = bch[u];
    const float* ht = out + (size_t)OFF_EMB + (size_t)bc*512;
    float* ef = out + (size_t)OFF_EF + (size_t)u*2050;
    for (int j = threadIdx.x; j < 512; j += blockDim.x) {
        float h = ht[j], f = g_hf[j];
        float ab = fabsf(f - h), pr = f*h;
        ef[j] = f; ef[512 + j] = h; ef[1024 + j] = ab; ef[1536 + j] = pr;
        __nv_bfloat16 hh, hl, ah, al;
        split_bf(h, hh, hl); split_bf(ab, ah, al);
        gA_hi[(size_t)u*1024 + j]       = hh;
        gA_lo[(size_t)u*1024 + j]       = hl;
        gA_hi[(size_t)u*1024 + 512 + j] = ah;
        gA_lo[(size_t)u*1024 + 512 + j] = al;
    }
    if (threadIdx.x == 0) { ef[2048] = tval[u]; ef[2049] = isroot[u]; }
}

// ----------------------------- head ------------------------------------------
__global__ void k_logits(const float* __restrict__ W3, const float* __restrict__ b3,
                         float* __restrict__ out) {
    int w = (blockIdx.x * blockDim.x + threadIdx.x) >> 5;
    int lane = threadIdx.x & 31;
    if (w >= NNODE) return;
    const float* z = g_Z2 + (size_t)w*512;
    float s = 0.f;
    #pragma unroll 4
    for (int j = lane; j < 512; j += 32) s += z[j]*W3[j];
    #pragma unroll
    for (int off = 16; off; off >>= 1) s += __shfl_down_sync(0xffffffffu, s, off);
    if (lane == 0) out[w] = s + b3[0];
}

__global__ void k_softmax(float* __restrict__ out) {
    __shared__ float red[1024];
    int tid = threadIdx.x;
    float m = -1e30f;
    for (int i = tid; i < NNODE; i += 1024) m = fmaxf(m, out[i]);
    red[tid] = m; __syncthreads();
    for (int s = 512; s; s >>= 1) {
        if (tid < s) red[tid] = fmaxf(red[tid], red[tid + s]);
        __syncthreads();
    }
    float M = red[0]; __syncthreads();
    float sum = 0.f;
    for (int i = tid; i < NNODE; i += 1024) sum += __expf(out[i] - M);
    red[tid] = sum; __syncthreads();
    for (int s = 512; s; s >>= 1) {
        if (tid < s) red[tid] += red[tid + s];
        __syncthreads();
    }
    float inv = 1.f / red[0];
    for (int i = tid; i < NNODE; i += 1024)
        out[NNODE + i] = __expf(out[i] - M) * inv;
}

// ----------------------------- launcher --------------------------------------
extern "C" void kernel_launch(void* const* d_in, const int* in_sizes, int n_in,
                              void* d_out, int out_size) {
    const int*   ns     = (const int*)d_in[0];
    const int*   ch0    = (const int*)d_in[1];
    const int*   ch1    = (const int*)d_in[2];
    const int*   parent = (const int*)d_in[3];
    const int*   neigh  = (const int*)d_in[4];
    const int*   bch    = (const int*)d_in[5];
    const int*   focal  = (const int*)d_in[6];
    const float* tv     = (const float*)d_in[7];
    const float* isroot = (const float*)d_in[8];
    const float* W1     = (const float*)d_in[9];
    const float* b1     = (const float*)d_in[10];
    const float* W2     = (const float*)d_in[11];
    const float* b2     = (const float*)d_in[12];
    const float* Wh1    = (const float*)d_in[13];
    const float* bh1    = (const float*)d_in[14];
    const float* Wh2    = (const float*)d_in[15];
    const float* bh2    = (const float*)d_in[16];
    const float* Wh3    = (const float*)d_in[17];
    const float* bh3    = (const float*)d_in[18];
    float* out = (float*)d_out;

    k_reset<<<16, 1024>>>(focal, out);
    k_leafinit<<<NLEAF + 1, 128>>>(ns, focal, W1);
    k_tree<<<512, 256>>>(ch0, ch1, parent);
    k_agg<<<NROW, 128>>>(0, neigh, b1);
    k_agg<<<NROW, 128>>>(1, neigh, b1);
    k_splitB<<<512, 256>>>(W2, 512, 0);

    dim3 gm(4, 64);
    // GEMM0: emb = Agg(h) @ W2 + b2
    k_mma<<<gm, 256>>>(0, NROW, 512, b2,
                       nullptr, nullptr, nullptr, nullptr, out + OFF_EMB);
    k_hf<<<1, 512>>>(out);
    k_cvec<<<1, 512>>>(Wh1, bh1);
    k_buildB<<<1024, 256>>>(Wh1);
    k_splitB<<<512, 256>>>(nullptr, 1024, 1);   // from g_Bm (device symbol)
    k_xef<<<NNODE, 256>>>(out, bch, tv, isroot);
    // GEMM1: Z1 = elu([h_t,|h_f-h_t|] @ Bm + cvec + t*wt + r*isroot)
    k_mma<<<gm, 256>>>(1, NNODE, 1024, nullptr,
                       Wh1 + (size_t)2048*512, Wh1 + (size_t)2049*512,
                       tv, isroot, nullptr);
    k_splitB<<<512, 256>>>(Wh2, 512, 0);
    // GEMM2: Z2 = elu(Z1 @ Wh2 + bh2)
    k_mma<<<gm, 256>>>(2, NNODE, 512, bh2,
                       nullptr, nullptr, nullptr, nullptr, nullptr);
    k_logits<<<256, 1024>>>(Wh3, bh3, out);
    k_softmax<<<1, 1024>>>(out);
}

// round 9
// speedup vs baseline: 1.5924x; 1.0564x over previous
#include <cuda_runtime.h>
#include <cuda_bf16.h>
#include <cstdint>

#define NLEAF 4096
#define NNODE 8191
#define NROW  8192
#define HID   512

#define OFF_EF     16382
#define OFF_EMB    16807932
#define OFF_FOCAL  21002236

// ----------------------------- scratch ---------------------------------------
__device__ float g_dW[NROW*HID];
__device__ float g_h[NROW*HID];
__device__ float g_Z2[NROW*HID];
__device__ float g_cvec[HID];
__device__ float g_hf[HID];
__device__ float g_c[NNODE];          // leaves stay 0 forever
__device__ int   g_postF[NNODE];
__device__ int   g_preF[NNODE];

// bf16 split operand buffers (k-contiguous)
__device__ __nv_bfloat16 gA_hi[(size_t)NROW*1024];
__device__ __nv_bfloat16 gA_lo[(size_t)NROW*1024];
__device__ __nv_bfloat16 gZ_hi[(size_t)NROW*512];
__device__ __nv_bfloat16 gZ_lo[(size_t)NROW*512];
__device__ __nv_bfloat16 gB0_hi[(size_t)512*1024];   // W2   [n][k]
__device__ __nv_bfloat16 gB0_lo[(size_t)512*1024];
__device__ __nv_bfloat16 gB1_hi[(size_t)512*1024];   // Bm   [n][k]
__device__ __nv_bfloat16 gB1_lo[(size_t)512*1024];
__device__ __nv_bfloat16 gB2_hi[(size_t)512*1024];   // Wh2  [n][k]
__device__ __nv_bfloat16 gB2_lo[(size_t)512*1024];

// ----------------------------- helpers ----------------------------------------
__device__ __forceinline__ void st_rel(int* p, int v) {
    asm volatile("st.release.gpu.global.b32 [%0], %1;" :: "l"(p), "r"(v) : "memory");
}
__device__ __forceinline__ int ld_acq(const int* p) {
    int v;
    asm volatile("ld.acquire.gpu.global.b32 %0, [%1];" : "=r"(v) : "l"(p) : "memory");
    return v;
}
__device__ __forceinline__ void split_bf(float v, __nv_bfloat16 &h, __nv_bfloat16 &l) {
    h = __float2bfloat16(v);
    l = __float2bfloat16(v - __bfloat162float(h));
}
__device__ __forceinline__ float eluf(float x) { return x > 0.f ? x : expm1f(x); }

__device__ __forceinline__ void mma_bf16(float* d, const uint32_t* a, uint32_t b0, uint32_t b1) {
    asm volatile(
        "mma.sync.aligned.m16n8k16.row.col.f32.bf16.bf16.f32 "
        "{%0,%1,%2,%3}, {%4,%5,%6,%7}, {%8,%9}, {%0,%1,%2,%3};"
        : "+f"(d[0]), "+f"(d[1]), "+f"(d[2]), "+f"(d[3])
        : "r"(a[0]), "r"(a[1]), "r"(a[2]), "r"(a[3]), "r"(b0), "r"(b1));
}

// ----------------------------- launch 1: split W2 & Wh2 + reset flags ---------
__global__ void k_splitB2(const float* __restrict__ W2, const float* __restrict__ Wh2) {
    int b = blockIdx.x;                 // 0..1023
    if (b < 64) {                       // reset sync flags for this call
        int i = b*256 + threadIdx.x;    // covers 16384 >= 2*NNODE
        if (i < NNODE) g_postF[i] = 0;
        else if (i < 2*NNODE) g_preF[i - NNODE] = 0;
    }
    const float* W = (b < 512) ? W2 : Wh2;
    __nv_bfloat16* bh = (b < 512) ? gB0_hi : gB2_hi;
    __nv_bfloat16* bl = (b < 512) ? gB0_lo : gB2_lo;
    int n = b & 511;
    for (int k = threadIdx.x; k < 512; k += blockDim.x) {
        float v = W[(size_t)k*512 + n];
        __nv_bfloat16 h, l; split_bf(v, h, l);
        bh[(size_t)n*1024 + k] = h;
        bl[(size_t)n*1024 + k] = l;
    }
}

// ----------------------------- launch 2: init leaf rows + focal ---------------
__global__ void k_init(const int* __restrict__ ns, const int* __restrict__ focal,
                       const float* __restrict__ W1, float* __restrict__ out) {
    int b = blockIdx.x;                 // 0..NLEAF (last = focal row)
    int u, src;
    if (b == NLEAF) { u = NNODE; src = focal[0]; }
    else {
        u = b; src = ns[b];
        if (threadIdx.x == 0) out[OFF_FOCAL + b] = (b == focal[0]) ? 1.f : 0.f;
        if (src < 0) return;
    }
    const float4* w = (const float4*)(W1 + (size_t)src*HID);
    float4* d = (float4*)(g_dW + (size_t)u*HID);
    d[threadIdx.x] = w[threadIdx.x];
}

// ----------------------------- launch 3: tree recursion (R7-proven) -----------
__global__ void k_tree(const int* __restrict__ ch0, const int* __restrict__ ch1,
                       const int* __restrict__ parent) {
    const int w    = blockIdx.x * (blockDim.x >> 5) + (threadIdx.x >> 5);
    const int lane = threadIdx.x & 31;
    const int NI   = NNODE - NLEAF;
    const int root = NNODE - 1;
    if (w >= NI) return;
    const int u = NLEAF + w;
    const int a = ch0[u], b = ch1[u];

    if (a >= NLEAF) while (!ld_acq(&g_postF[a])) __nanosleep(32);
    if (b >= NLEAF) while (!ld_acq(&g_postF[b])) __nanosleep(32);
    __syncwarp();
    float ca = __ldcg(&g_c[a]);
    float cb = __ldcg(&g_c[b]);
    float cu = 1.f / (3.f - ca - cb);
    const float4* pa = (const float4*)(g_dW + (size_t)a*HID);
    const float4* pb = (const float4*)(g_dW + (size_t)b*HID);
    float4*       pu = (float4*)(g_dW + (size_t)u*HID);
    #pragma unroll
    for (int j = 0; j < 4; j++) {
        int c4 = lane + j*32;
        float4 x = __ldcg(pa + c4), y = __ldcg(pb + c4), r;
        r.x = cu*(x.x+y.x); r.y = cu*(x.y+y.y);
        r.z = cu*(x.z+y.z); r.w = cu*(x.w+y.w);
        pu[c4] = r;
    }
    if (lane == 0) g_c[u] = cu;
    __threadfence();
    __syncwarp();
    if (lane == 0) {
        st_rel(&g_postF[u], 1);
        if (u == root) st_rel(&g_preF[u], 1);
    }
    __syncwarp();
    if (u == root) return;

    const int p = parent[u];
    while (!ld_acq(&g_preF[p])) __nanosleep(32);
    __syncwarp();
    const float4* pp = (const float4*)(g_dW + (size_t)p*HID);
    #pragma unroll
    for (int j = 0; j < 4; j++) {
        int c4 = lane + j*32;
        float4 x = __ldcg(pp + c4);
        float4 r = pu[c4];
        r.x += cu*x.x; r.y += cu*x.y; r.z += cu*x.z; r.w += cu*x.w;
        pu[c4] = r;
    }
    __threadfence();
    __syncwarp();
    if (lane == 0) st_rel(&g_preF[u], 1);
}

// ----------------------------- launches 4,5: GCN aggregation ------------------
__global__ void k_agg(int phase, const int* __restrict__ neigh,
                      const float* __restrict__ bias) {
    const float* src = (phase == 0) ? g_dW : g_h;
    int u = blockIdx.x;
    int n0 = neigh[3*u], n1 = neigh[3*u+1], n2 = neigh[3*u+2];
    float inv = 1.f / (1.f + (n0 >= 0) + (n1 >= 0) + (n2 >= 0));
    const float4* s  = (const float4*)(src + (size_t)u*HID);
    const float4* p0 = (const float4*)(src + (size_t)(n0 >= 0 ? n0 : 0)*HID);
    const float4* p1 = (const float4*)(src + (size_t)(n1 >= 0 ? n1 : 0)*HID);
    const float4* p2 = (const float4*)(src + (size_t)(n2 >= 0 ? n2 : 0)*HID);
    int j = threadIdx.x;
    float4 v = s[j];
    if (n0 >= 0) { float4 t = p0[j]; v.x += t.x; v.y += t.y; v.z += t.z; v.w += t.w; }
    if (n1 >= 0) { float4 t = p1[j]; v.x += t.x; v.y += t.y; v.z += t.z; v.w += t.w; }
    if (n2 >= 0) { float4 t = p2[j]; v.x += t.x; v.y += t.y; v.z += t.z; v.w += t.w; }
    v.x *= inv; v.y *= inv; v.z *= inv; v.w *= inv;
    if (phase == 0) {
        float4 b = ((const float4*)bias)[j];
        v.x = fmaxf(v.x + b.x, 0.f); v.y = fmaxf(v.y + b.y, 0.f);
        v.z = fmaxf(v.z + b.z, 0.f); v.w = fmaxf(v.w + b.w, 0.f);
        ((float4*)(g_h + (size_t)u*HID))[j] = v;
    } else {
        __nv_bfloat16 h0,l0,h1,l1,h2,l2,h3,l3;
        split_bf(v.x, h0, l0); split_bf(v.y, h1, l1);
        split_bf(v.z, h2, l2); split_bf(v.w, h3, l3);
        ushort4 sh = { __bfloat16_as_ushort(h0), __bfloat16_as_ushort(h1),
                       __bfloat16_as_ushort(h2), __bfloat16_as_ushort(h3) };
        ushort4 sl = { __bfloat16_as_ushort(l0), __bfloat16_as_ushort(l1),
                       __bfloat16_as_ushort(l2), __bfloat16_as_ushort(l3) };
        *(ushort4*)(gA_hi + (size_t)u*1024 + 4*j) = sh;
        *(ushort4*)(gA_lo + (size_t)u*1024 + 4*j) = sl;
    }
}

// ----------------------------- mma.sync bf16x3 GEMM ---------------------------
// mode 0: A=gA (stride 1024), B=gB0, K=512 ; Cout = D + bias (fp32)
// mode 1: A=gA (stride 1024), B=gB1, K=1024; gZ = split(elu(D + cvec + t*wt + r*wr))
// mode 2: A=gZ (stride 512),  B=gB2, K=512 ; g_Z2 = elu(D + bias)
#define SROW 40   // smem row stride in bf16 (80B)
__global__ __launch_bounds__(256, 2) void k_mma(
        int mode, int M, int K,
        const float* __restrict__ bias,
        const float* __restrict__ wt, const float* __restrict__ wr,
        const float* __restrict__ tv, const float* __restrict__ rv,
        float* __restrict__ Cout) {
    const __nv_bfloat16* Ahi = (mode == 2) ? gZ_hi : gA_hi;
    const __nv_bfloat16* Alo = (mode == 2) ? gZ_lo : gA_lo;
    const __nv_bfloat16* Bhi = (mode == 0) ? gB0_hi : (mode == 1 ? gB1_hi : gB2_hi);
    const __nv_bfloat16* Blo = (mode == 0) ? gB0_lo : (mode == 1 ? gB1_lo : gB2_lo);
    const int strideA = (mode == 2) ? 512 : 1024;

    __shared__ __align__(16) __nv_bfloat16 sm[4*128*SROW];   // 40960 B: Ah, Al, Bh, Bl
    const int tid  = threadIdx.x;
    const int wid  = tid >> 5;
    const int lane = tid & 31;
    const int gid  = lane >> 2;       // 0..7
    const int tig  = lane & 3;        // 0..3
    const int m0 = blockIdx.y * 128;
    const int n0 = blockIdx.x * 128;
    const int wm = (wid & 3) * 32;    // warp m offset
    const int wn = (wid >> 2) * 64;   // warp n offset
    const int Cn = K >> 5;            // 32-wide K chunks

    float acc[2][8][4];
    #pragma unroll
    for (int i = 0; i < 2; i++)
        #pragma unroll
        for (int j = 0; j < 8; j++)
            #pragma unroll
            for (int q = 0; q < 4; q++) acc[i][j][q] = 0.f;

    uint4 rAh[2], rAl[2], rBh[2], rBl[2];
    auto load_g = [&](int c) {
        const size_t kb = (size_t)c * 32;
        #pragma unroll
        for (int it = 0; it < 2; it++) {
            int idx = it*256 + tid;
            int row = idx >> 2, seg = idx & 3;
            rAh[it] = *(const uint4*)(Ahi + (size_t)(m0+row)*strideA + kb + seg*8);
            rAl[it] = *(const uint4*)(Alo + (size_t)(m0+row)*strideA + kb + seg*8);
            rBh[it] = *(const uint4*)(Bhi + (size_t)(n0+row)*1024 + kb + seg*8);
            rBl[it] = *(const uint4*)(Blo + (size_t)(n0+row)*1024 + kb + seg*8);
        }
    };
    auto store_s = [&]() {
        #pragma unroll
        for (int it = 0; it < 2; it++) {
            int idx = it*256 + tid;
            int row = idx >> 2, seg = idx & 3;
            int so = row*SROW + seg*8;
            *(uint4*)(sm + 0*128*SROW + so) = rAh[it];
            *(uint4*)(sm + 1*128*SROW + so) = rAl[it];
            *(uint4*)(sm + 2*128*SROW + so) = rBh[it];
            *(uint4*)(sm + 3*128*SROW + so) = rBl[it];
        }
    };

    load_g(0);
    for (int c = 0; c < Cn; c++) {
        store_s();
        __syncthreads();
        if (c + 1 < Cn) load_g(c + 1);     // global->reg prefetch overlaps compute
        const __nv_bfloat16* sAh = sm;
        const __nv_bfloat16* sAl = sm + 128*SROW;
        const __nv_bfloat16* sBh = sm + 2*128*SROW;
        const __nv_bfloat16* sBl = sm + 3*128*SROW;
        #pragma unroll
        for (int ks = 0; ks < 32; ks += 16) {
            uint32_t aH[2][4], aL[2][4];
            #pragma unroll
            for (int i = 0; i < 2; i++) {
                int rb = wm + i*16 + gid;
                int cb = ks + tig*2;
                aH[i][0] = *(const uint32_t*)(sAh + rb*SROW + cb);
                aH[i][1] = *(const uint32_t*)(sAh + (rb+8)*SROW + cb);
                aH[i][2] = *(const uint32_t*)(sAh + rb*SROW + cb + 8);
                aH[i][3] = *(const uint32_t*)(sAh + (rb+8)*SROW + cb + 8);
                aL[i][0] = *(const uint32_t*)(sAl + rb*SROW + cb);
                aL[i][1] = *(const uint32_t*)(sAl + (rb+8)*SROW + cb);
                aL[i][2] = *(const uint32_t*)(sAl + rb*SROW + cb + 8);
                aL[i][3] = *(const uint32_t*)(sAl + (rb+8)*SROW + cb + 8);
            }
            #pragma unroll
            for (int j = 0; j < 8; j++) {
                int nb = wn + j*8 + gid;
                int cb = ks + tig*2;
                uint32_t bh0 = *(const uint32_t*)(sBh + nb*SROW + cb);
                uint32_t bh1 = *(const uint32_t*)(sBh + nb*SROW + cb + 8);
                uint32_t bl0 = *(const uint32_t*)(sBl + nb*SROW + cb);
                uint32_t bl1 = *(const uint32_t*)(sBl + nb*SROW + cb + 8);
                #pragma unroll
                for (int i = 0; i < 2; i++) {
                    mma_bf16(acc[i][j], aH[i], bh0, bh1);
                    mma_bf16(acc[i][j], aH[i], bl0, bl1);
                    mma_bf16(acc[i][j], aL[i], bh0, bh1);
                }
            }
        }
        __syncthreads();
    }

    // ----- epilogue -----
    #pragma unroll
    for (int i = 0; i < 2; i++) {
        #pragma unroll
        for (int r2 = 0; r2 < 2; r2++) {
            int m = m0 + wm + i*16 + gid + r2*8;
            if (m >= M) continue;
            float t = 0.f, r = 0.f;
            if (mode == 1) { t = tv[m]; r = rv[m]; }
            #pragma unroll
            for (int j = 0; j < 8; j++) {
                int n = n0 + wn + j*8 + tig*2;
                float v0 = acc[i][j][r2*2 + 0];
                float v1 = acc[i][j][r2*2 + 1];
                if (mode == 0) {
                    float2 bv = *(const float2*)&bias[n];
                    *(float2*)(Cout + (size_t)m*512 + n) = make_float2(v0 + bv.x, v1 + bv.y);
                } else if (mode == 1) {
                    float2 cv = *(const float2*)&g_cvec[n];
                    float2 wtv = *(const float2*)&wt[n];
                    float2 wrv = *(const float2*)&wr[n];
                    float z0 = eluf(v0 + cv.x + t*wtv.x + r*wrv.x);
                    float z1 = eluf(v1 + cv.y + t*wtv.y + r*wrv.y);
                    __nv_bfloat16 h0, l0, h1, l1;
                    split_bf(z0, h0, l0); split_bf(z1, h1, l1);
                    ushort2 sh = { __bfloat16_as_ushort(h0), __bfloat16_as_ushort(h1) };
                    ushort2 sl = { __bfloat16_as_ushort(l0), __bfloat16_as_ushort(l1) };
                    *(ushort2*)(gZ_hi + (size_t)m*512 + n) = sh;
                    *(ushort2*)(gZ_lo + (size_t)m*512 + n) = sl;
                } else {
                    float2 bv = *(const float2*)&bias[n];
                    *(float2*)(g_Z2 + (size_t)m*512 + n) =
                        make_float2(eluf(v0 + bv.x), eluf(v1 + bv.y));
                }
            }
        }
    }
}

// ----------------------------- launch 7: hf + cvec ----------------------------
__global__ void k_hfcvec(const float* __restrict__ out, const float* __restrict__ W1h,
                         const float* __restrict__ bh1) {
    __shared__ float sh[HID];
    int t = threadIdx.x;
    float hv = out[(size_t)OFF_EMB + (size_t)NNODE*HID + t];
    g_hf[t] = hv;
    sh[t] = hv;
    __syncthreads();
    float s = bh1[t];
    for (int k = 0; k < HID; k++) s += sh[k] * W1h[(size_t)k*512 + t];
    g_cvec[t] = s;
}

// ----------------------------- launch 8: build Bm + split → gB1 ---------------
__global__ void k_buildsplit(const float* __restrict__ W1h) {
    int n = blockIdx.x;            // 0..511
    for (int k = threadIdx.x; k < 1024; k += blockDim.x) {
        float v = W1h[(size_t)(512 + k)*512 + n];
        if (k < 512) v += g_hf[k] * W1h[(size_t)(1536 + k)*512 + n];
        __nv_bfloat16 h, l; split_bf(v, h, l);
        gB1_hi[(size_t)n*1024 + k] = h;
        gB1_lo[(size_t)n*1024 + k] = l;
    }
}

// ----------------------------- launch 9: ef + X split -------------------------
__global__ void k_xef(float* __restrict__ out, const int* __restrict__ bch,
                      const float* __restrict__ tval, const float* __restrict__ isroot) {
    int u = blockIdx.x;
    int bc = bch[u];
    const float* ht = out + (size_t)OFF_EMB + (size_t)bc*512;
    float* ef = out + (size_t)OFF_EF + (size_t)u*2050;
    for (int j = threadIdx.x; j < 512; j += blockDim.x) {
        float h = ht[j], f = g_hf[j];
        float ab = fabsf(f - h), pr = f*h;
        ef[j] = f; ef[512 + j] = h; ef[1024 + j] = ab; ef[1536 + j] = pr;
        __nv_bfloat16 hh, hl, ah, al;
        split_bf(h, hh, hl); split_bf(ab, ah, al);
        gA_hi[(size_t)u*1024 + j]       = hh;
        gA_lo[(size_t)u*1024 + j]       = hl;
        gA_hi[(size_t)u*1024 + 512 + j] = ah;
        gA_lo[(size_t)u*1024 + 512 + j] = al;
    }
    if (threadIdx.x == 0) { ef[2048] = tval[u]; ef[2049] = isroot[u]; }
}

// ----------------------------- head ------------------------------------------
__global__ void k_logits(const float* __restrict__ W3, const float* __restrict__ b3,
                         float* __restrict__ out) {
    int w = (blockIdx.x * blockDim.x + threadIdx.x) >> 5;
    int lane = threadIdx.x & 31;
    if (w >= NNODE) return;
    const float* z = g_Z2 + (size_t)w*512;
    float s = 0.f;
    #pragma unroll 4
    for (int j = lane; j < 512; j += 32) s += z[j]*W3[j];
    #pragma unroll
    for (int off = 16; off; off >>= 1) s += __shfl_down_sync(0xffffffffu, s, off);
    if (lane == 0) out[w] = s + b3[0];
}

__global__ void k_softmax(float* __restrict__ out) {
    __shared__ float red[1024];
    int tid = threadIdx.x;
    float m = -1e30f;
    for (int i = tid; i < NNODE; i += 1024) m = fmaxf(m, out[i]);
    red[tid] = m; __syncthreads();
    for (int s = 512; s; s >>= 1) {
        if (tid < s) red[tid] = fmaxf(red[tid], red[tid + s]);
        __syncthreads();
    }
    float M = red[0]; __syncthreads();
    float sum = 0.f;
    for (int i = tid; i < NNODE; i += 1024) sum += __expf(out[i] - M);
    red[tid] = sum; __syncthreads();
    for (int s = 512; s; s >>= 1) {
        if (tid < s) red[tid] += red[tid + s];
        __syncthreads();
    }
    float inv = 1.f / red[0];
    for (int i = tid; i < NNODE; i += 1024)
        out[NNODE + i] = __expf(out[i] - M) * inv;
}

// ----------------------------- launcher --------------------------------------
extern "C" void kernel_launch(void* const* d_in, const int* in_sizes, int n_in,
                              void* d_out, int out_size) {
    const int*   ns     = (const int*)d_in[0];
    const int*   ch0    = (const int*)d_in[1];
    const int*   ch1    = (const int*)d_in[2];
    const int*   parent = (const int*)d_in[3];
    const int*   neigh  = (const int*)d_in[4];
    const int*   bch    = (const int*)d_in[5];
    const int*   focal  = (const int*)d_in[6];
    const float* tv     = (const float*)d_in[7];
    const float* isroot = (const float*)d_in[8];
    const float* W1     = (const float*)d_in[9];
    const float* b1     = (const float*)d_in[10];
    const float* W2     = (const float*)d_in[11];
    const float* b2     = (const float*)d_in[12];
    const float* Wh1    = (const float*)d_in[13];
    const float* bh1    = (const float*)d_in[14];
    const float* Wh2    = (const float*)d_in[15];
    const float* bh2    = (const float*)d_in[16];
    const float* Wh3    = (const float*)d_in[17];
    const float* bh3    = (const float*)d_in[18];
    float* out = (float*)d_out;

    dim3 gm(4, 64);
    k_splitB2<<<1024, 256>>>(W2, Wh2);                 // 1 (also resets flags)
    k_init<<<NLEAF + 1, 128>>>(ns, focal, W1, out);    // 2
    k_tree<<<512, 256>>>(ch0, ch1, parent);            // 3
    k_agg<<<NROW, 128>>>(0, neigh, b1);                // 4
    k_agg<<<NROW, 128>>>(1, neigh, b1);                // 5
    // 6 (profiled): GEMM0: emb = Agg(h) @ W2 + b2
    k_mma<<<gm, 256>>>(0, NROW, 512, b2,
                       nullptr, nullptr, nullptr, nullptr, out + OFF_EMB);
    k_hfcvec<<<1, 512>>>(out, Wh1, bh1);               // 7
    k_buildsplit<<<512, 256>>>(Wh1);                   // 8
    k_xef<<<NNODE, 256>>>(out, bch, tv, isroot);       // 9
    // 10: GEMM1
    k_mma<<<gm, 256>>>(1, NNODE, 1024, nullptr,
                       Wh1 + (size_t)2048*512, Wh1 + (size_t)2049*512,
                       tv, isroot, nullptr);
    // 11: GEMM2
    k_mma<<<gm, 256>>>(2, NNODE, 512, bh2,
                       nullptr, nullptr, nullptr, nullptr, nullptr);
    k_logits<<<256, 1024>>>(Wh3, bh3, out);            // 12
    k_softmax<<<1, 1024>>>(out);                       // 13
}

// round 10
// speedup vs baseline: 1.6727x; 1.0504x over previous
#include <cuda_runtime.h>
#include <cuda_bf16.h>
#include <cstdint>

#define NLEAF 4096
#define NNODE 8191
#define NROW  8192
#define HID   512

#define OFF_EF     16382
#define OFF_EMB    16807932
#define OFF_FOCAL  21002236

// ----------------------------- scratch ---------------------------------------
__device__ float g_dW[NROW*HID];
__device__ float g_h[NROW*HID];
__device__ float g_Z2[NROW*HID];
__device__ float g_cvec[HID];
__device__ float g_hf[HID];
__device__ float g_c[NNODE];          // leaves stay 0 forever
__device__ int   g_postF[NNODE];
__device__ int   g_preF[NNODE];

// bf16 split operand buffers (k-contiguous)
__device__ __nv_bfloat16 gA_hi[(size_t)NROW*1024];
__device__ __nv_bfloat16 gA_lo[(size_t)NROW*1024];
__device__ __nv_bfloat16 gZ_hi[(size_t)NROW*512];
__device__ __nv_bfloat16 gZ_lo[(size_t)NROW*512];
__device__ __nv_bfloat16 gB0_hi[(size_t)512*1024];   // W2   [n][k]
__device__ __nv_bfloat16 gB0_lo[(size_t)512*1024];
__device__ __nv_bfloat16 gB1_hi[(size_t)512*1024];   // Bm   [n][k]
__device__ __nv_bfloat16 gB1_lo[(size_t)512*1024];
__device__ __nv_bfloat16 gB2_hi[(size_t)512*1024];   // Wh2  [n][k]
__device__ __nv_bfloat16 gB2_lo[(size_t)512*1024];

// ----------------------------- helpers ----------------------------------------
__device__ __forceinline__ void st_rel(int* p, int v) {
    asm volatile("st.release.gpu.global.b32 [%0], %1;" :: "l"(p), "r"(v) : "memory");
}
__device__ __forceinline__ int ld_acq(const int* p) {
    int v;
    asm volatile("ld.acquire.gpu.global.b32 %0, [%1];" : "=r"(v) : "l"(p) : "memory");
    return v;
}
__device__ __forceinline__ void split_bf(float v, __nv_bfloat16 &h, __nv_bfloat16 &l) {
    h = __float2bfloat16(v);
    l = __float2bfloat16(v - __bfloat162float(h));
}
__device__ __forceinline__ float eluf(float x) { return x > 0.f ? x : expm1f(x); }

__device__ __forceinline__ void mma_bf16(float* d, const uint32_t* a, uint32_t b0, uint32_t b1) {
    asm volatile(
        "mma.sync.aligned.m16n8k16.row.col.f32.bf16.bf16.f32 "
        "{%0,%1,%2,%3}, {%4,%5,%6,%7}, {%8,%9}, {%0,%1,%2,%3};"
        : "+f"(d[0]), "+f"(d[1]), "+f"(d[2]), "+f"(d[3])
        : "r"(a[0]), "r"(a[1]), "r"(a[2]), "r"(a[3]), "r"(b0), "r"(b1));
}

// ----------------------------- launch 1: prep ---------------------------------
// blocks 0..1023   : split W2 (0..511) / Wh2 (512..1023) into gB0/gB2; b<64 reset flags
// blocks 1024..5120: leaf-row init (+focal one-hot & focal row at block 5120)
__global__ void k_prep(const float* __restrict__ W2, const float* __restrict__ Wh2,
                       const int* __restrict__ ns, const int* __restrict__ focal,
                       const float* __restrict__ W1, float* __restrict__ out) {
    int b = blockIdx.x;
    if (b < 1024) {
        if (b < 64) {
            int i = b*256 + threadIdx.x;    // covers 16384 >= 2*NNODE
            if (i < NNODE) g_postF[i] = 0;
            else if (i < 2*NNODE) g_preF[i - NNODE] = 0;
        }
        const float* W = (b < 512) ? W2 : Wh2;
        __nv_bfloat16* bh = (b < 512) ? gB0_hi : gB2_hi;
        __nv_bfloat16* bl = (b < 512) ? gB0_lo : gB2_lo;
        int n = b & 511;
        for (int k = threadIdx.x; k < 512; k += blockDim.x) {
            float v = W[(size_t)k*512 + n];
            __nv_bfloat16 h, l; split_bf(v, h, l);
            bh[(size_t)n*1024 + k] = h;
            bl[(size_t)n*1024 + k] = l;
        }
        return;
    }
    int bb = b - 1024;                      // 0..4096
    int u, src;
    if (bb == NLEAF) { u = NNODE; src = focal[0]; }
    else {
        u = bb; src = ns[bb];
        if (threadIdx.x == 0) out[OFF_FOCAL + bb] = (bb == focal[0]) ? 1.f : 0.f;
        if (src < 0) return;
    }
    if (threadIdx.x < 128) {
        const float4* w = (const float4*)(W1 + (size_t)src*HID);
        float4* d = (float4*)(g_dW + (size_t)u*HID);
        d[threadIdx.x] = w[threadIdx.x];
    }
}

// ----------------------------- launch 2: tree recursion -----------------------
__global__ void k_tree(const int* __restrict__ ch0, const int* __restrict__ ch1,
                       const int* __restrict__ parent) {
    const int w    = blockIdx.x * (blockDim.x >> 5) + (threadIdx.x >> 5);
    const int lane = threadIdx.x & 31;
    const int NI   = NNODE - NLEAF;
    const int root = NNODE - 1;
    if (w >= NI) return;
    const int u = NLEAF + w;
    const int a = ch0[u], b = ch1[u];

    if (a >= NLEAF) while (!ld_acq(&g_postF[a])) __nanosleep(32);
    if (b >= NLEAF) while (!ld_acq(&g_postF[b])) __nanosleep(32);
    __syncwarp();
    float ca = __ldcg(&g_c[a]);
    float cb = __ldcg(&g_c[b]);
    float cu = 1.f / (3.f - ca - cb);
    const float4* pa = (const float4*)(g_dW + (size_t)a*HID);
    const float4* pb = (const float4*)(g_dW + (size_t)b*HID);
    float4*       pu = (float4*)(g_dW + (size_t)u*HID);
    #pragma unroll
    for (int j = 0; j < 4; j++) {
        int c4 = lane + j*32;
        float4 x = __ldcg(pa + c4), y = __ldcg(pb + c4), r;
        r.x = cu*(x.x+y.x); r.y = cu*(x.y+y.y);
        r.z = cu*(x.z+y.z); r.w = cu*(x.w+y.w);
        pu[c4] = r;
    }
    if (lane == 0) g_c[u] = cu;
    __threadfence();
    __syncwarp();
    if (lane == 0) {
        st_rel(&g_postF[u], 1);
        if (u == root) st_rel(&g_preF[u], 1);
    }
    __syncwarp();
    if (u == root) return;

    const int p = parent[u];
    while (!ld_acq(&g_preF[p])) __nanosleep(32);
    __syncwarp();
    const float4* pp = (const float4*)(g_dW + (size_t)p*HID);
    #pragma unroll
    for (int j = 0; j < 4; j++) {
        int c4 = lane + j*32;
        float4 x = __ldcg(pp + c4);
        float4 r = pu[c4];
        r.x += cu*x.x; r.y += cu*x.y; r.z += cu*x.z; r.w += cu*x.w;
        pu[c4] = r;
    }
    __threadfence();
    __syncwarp();
    if (lane == 0) st_rel(&g_preF[u], 1);
}

// ----------------------------- launches 3,4: GCN aggregation ------------------
__global__ void k_agg(int phase, const int* __restrict__ neigh,
                      const float* __restrict__ bias) {
    const float* src = (phase == 0) ? g_dW : g_h;
    int u = blockIdx.x;
    int n0 = neigh[3*u], n1 = neigh[3*u+1], n2 = neigh[3*u+2];
    float inv = 1.f / (1.f + (n0 >= 0) + (n1 >= 0) + (n2 >= 0));
    const float4* s  = (const float4*)(src + (size_t)u*HID);
    const float4* p0 = (const float4*)(src + (size_t)(n0 >= 0 ? n0 : 0)*HID);
    const float4* p1 = (const float4*)(src + (size_t)(n1 >= 0 ? n1 : 0)*HID);
    const float4* p2 = (const float4*)(src + (size_t)(n2 >= 0 ? n2 : 0)*HID);
    int j = threadIdx.x;
    float4 v = s[j];
    if (n0 >= 0) { float4 t = p0[j]; v.x += t.x; v.y += t.y; v.z += t.z; v.w += t.w; }
    if (n1 >= 0) { float4 t = p1[j]; v.x += t.x; v.y += t.y; v.z += t.z; v.w += t.w; }
    if (n2 >= 0) { float4 t = p2[j]; v.x += t.x; v.y += t.y; v.z += t.z; v.w += t.w; }
    v.x *= inv; v.y *= inv; v.z *= inv; v.w *= inv;
    if (phase == 0) {
        float4 b = ((const float4*)bias)[j];
        v.x = fmaxf(v.x + b.x, 0.f); v.y = fmaxf(v.y + b.y, 0.f);
        v.z = fmaxf(v.z + b.z, 0.f); v.w = fmaxf(v.w + b.w, 0.f);
        ((float4*)(g_h + (size_t)u*HID))[j] = v;
    } else {
        __nv_bfloat16 h0,l0,h1,l1,h2,l2,h3,l3;
        split_bf(v.x, h0, l0); split_bf(v.y, h1, l1);
        split_bf(v.z, h2, l2); split_bf(v.w, h3, l3);
        ushort4 sh = { __bfloat16_as_ushort(h0), __bfloat16_as_ushort(h1),
                       __bfloat16_as_ushort(h2), __bfloat16_as_ushort(h3) };
        ushort4 sl = { __bfloat16_as_ushort(l0), __bfloat16_as_ushort(l1),
                       __bfloat16_as_ushort(l2), __bfloat16_as_ushort(l3) };
        *(ushort4*)(gA_hi + (size_t)u*1024 + 4*j) = sh;
        *(ushort4*)(gA_lo + (size_t)u*1024 + 4*j) = sl;
    }
}

// ----------------------------- mma.sync bf16x3 GEMM ---------------------------
// mode 0: A=gA (stride 1024), B=gB0, K=512 ; Cout = D + bias (fp32)
// mode 1: A=gA (stride 1024), B=gB1, K=1024; gZ = split(elu(D + cvec + t*wt + r*wr))
// mode 2: A=gZ (stride 512),  B=gB2, K=512 ; g_Z2 = elu(D + bias)
#define SROW 40   // smem row stride in bf16 (80B)
__global__ __launch_bounds__(256, 2) void k_mma(
        int mode, int M, int K,
        const float* __restrict__ bias,
        const float* __restrict__ wt, const float* __restrict__ wr,
        const float* __restrict__ tv, const float* __restrict__ rv,
        float* __restrict__ Cout) {
    const __nv_bfloat16* Ahi = (mode == 2) ? gZ_hi : gA_hi;
    const __nv_bfloat16* Alo = (mode == 2) ? gZ_lo : gA_lo;
    const __nv_bfloat16* Bhi = (mode == 0) ? gB0_hi : (mode == 1 ? gB1_hi : gB2_hi);
    const __nv_bfloat16* Blo = (mode == 0) ? gB0_lo : (mode == 1 ? gB1_lo : gB2_lo);
    const int strideA = (mode == 2) ? 512 : 1024;

    __shared__ __align__(16) __nv_bfloat16 sm[4*128*SROW];   // 40960 B: Ah, Al, Bh, Bl
    const int tid  = threadIdx.x;
    const int wid  = tid >> 5;
    const int lane = tid & 31;
    const int gid  = lane >> 2;       // 0..7
    const int tig  = lane & 3;        // 0..3
    const int m0 = blockIdx.y * 128;
    const int n0 = blockIdx.x * 128;
    const int wm = (wid & 3) * 32;    // warp m offset
    const int wn = (wid >> 2) * 64;   // warp n offset
    const int Cn = K >> 5;            // 32-wide K chunks

    float acc[2][8][4];
    #pragma unroll
    for (int i = 0; i < 2; i++)
        #pragma unroll
        for (int j = 0; j < 8; j++)
            #pragma unroll
            for (int q = 0; q < 4; q++) acc[i][j][q] = 0.f;

    uint4 rAh[2], rAl[2], rBh[2], rBl[2];
    auto load_g = [&](int c) {
        const size_t kb = (size_t)c * 32;
        #pragma unroll
        for (int it = 0; it < 2; it++) {
            int idx = it*256 + tid;
            int row = idx >> 2, seg = idx & 3;
            rAh[it] = *(const uint4*)(Ahi + (size_t)(m0+row)*strideA + kb + seg*8);
            rAl[it] = *(const uint4*)(Alo + (size_t)(m0+row)*strideA + kb + seg*8);
            rBh[it] = *(const uint4*)(Bhi + (size_t)(n0+row)*1024 + kb + seg*8);
            rBl[it] = *(const uint4*)(Blo + (size_t)(n0+row)*1024 + kb + seg*8);
        }
    };
    auto store_s = [&]() {
        #pragma unroll
        for (int it = 0; it < 2; it++) {
            int idx = it*256 + tid;
            int row = idx >> 2, seg = idx & 3;
            int so = row*SROW + seg*8;
            *(uint4*)(sm + 0*128*SROW + so) = rAh[it];
            *(uint4*)(sm + 1*128*SROW + so) = rAl[it];
            *(uint4*)(sm + 2*128*SROW + so) = rBh[it];
            *(uint4*)(sm + 3*128*SROW + so) = rBl[it];
        }
    };

    load_g(0);
    for (int c = 0; c < Cn; c++) {
        store_s();
        __syncthreads();
        if (c + 1 < Cn) load_g(c + 1);     // global->reg prefetch overlaps compute
        const __nv_bfloat16* sAh = sm;
        const __nv_bfloat16* sAl = sm + 128*SROW;
        const __nv_bfloat16* sBh = sm + 2*128*SROW;
        const __nv_bfloat16* sBl = sm + 3*128*SROW;
        #pragma unroll
        for (int ks = 0; ks < 32; ks += 16) {
            uint32_t aH[2][4], aL[2][4];
            #pragma unroll
            for (int i = 0; i < 2; i++) {
                int rb = wm + i*16 + gid;
                int cb = ks + tig*2;
                aH[i][0] = *(const uint32_t*)(sAh + rb*SROW + cb);
                aH[i][1] = *(const uint32_t*)(sAh + (rb+8)*SROW + cb);
                aH[i][2] = *(const uint32_t*)(sAh + rb*SROW + cb + 8);
                aH[i][3] = *(const uint32_t*)(sAh + (rb+8)*SROW + cb + 8);
                aL[i][0] = *(const uint32_t*)(sAl + rb*SROW + cb);
                aL[i][1] = *(const uint32_t*)(sAl + (rb+8)*SROW + cb);
                aL[i][2] = *(const uint32_t*)(sAl + rb*SROW + cb + 8);
                aL[i][3] = *(const uint32_t*)(sAl + (rb+8)*SROW + cb + 8);
            }
            #pragma unroll
            for (int j = 0; j < 8; j++) {
                int nb = wn + j*8 + gid;
                int cb = ks + tig*2;
                uint32_t bh0 = *(const uint32_t*)(sBh + nb*SROW + cb);
                uint32_t bh1 = *(const uint32_t*)(sBh + nb*SROW + cb + 8);
                uint32_t bl0 = *(const uint32_t*)(sBl + nb*SROW + cb);
                uint32_t bl1 = *(const uint32_t*)(sBl + nb*SROW + cb + 8);
                #pragma unroll
                for (int i = 0; i < 2; i++) {
                    mma_bf16(acc[i][j], aH[i], bh0, bh1);
                    mma_bf16(acc[i][j], aH[i], bl0, bl1);
                    mma_bf16(acc[i][j], aL[i], bh0, bh1);
                }
            }
        }
        __syncthreads();
    }

    // ----- epilogue -----
    #pragma unroll
    for (int i = 0; i < 2; i++) {
        #pragma unroll
        for (int r2 = 0; r2 < 2; r2++) {
            int m = m0 + wm + i*16 + gid + r2*8;
            if (m >= M) continue;
            float t = 0.f, r = 0.f;
            if (mode == 1) { t = tv[m]; r = rv[m]; }
            #pragma unroll
            for (int j = 0; j < 8; j++) {
                int n = n0 + wn + j*8 + tig*2;
                float v0 = acc[i][j][r2*2 + 0];
                float v1 = acc[i][j][r2*2 + 1];
                if (mode == 0) {
                    float2 bv = *(const float2*)&bias[n];
                    *(float2*)(Cout + (size_t)m*512 + n) = make_float2(v0 + bv.x, v1 + bv.y);
                } else if (mode == 1) {
                    float2 cv = *(const float2*)&g_cvec[n];
                    float2 wtv = *(const float2*)&wt[n];
                    float2 wrv = *(const float2*)&wr[n];
                    float z0 = eluf(v0 + cv.x + t*wtv.x + r*wrv.x);
                    float z1 = eluf(v1 + cv.y + t*wtv.y + r*wrv.y);
                    __nv_bfloat16 h0, l0, h1, l1;
                    split_bf(z0, h0, l0); split_bf(z1, h1, l1);
                    ushort2 sh = { __bfloat16_as_ushort(h0), __bfloat16_as_ushort(h1) };
                    ushort2 sl = { __bfloat16_as_ushort(l0), __bfloat16_as_ushort(l1) };
                    *(ushort2*)(gZ_hi + (size_t)m*512 + n) = sh;
                    *(ushort2*)(gZ_lo + (size_t)m*512 + n) = sl;
                } else {
                    float2 bv = *(const float2*)&bias[n];
                    *(float2*)(g_Z2 + (size_t)m*512 + n) =
                        make_float2(eluf(v0 + bv.x), eluf(v1 + bv.y));
                }
            }
        }
    }
}

// ----------------------------- launch 6: hf + cvec (parallel) -----------------
// block n (0..511): cvec[n] = bh1[n] + sum_k emb_focal[k] * W1h[k*512+n]
// block 0 also stores g_hf.
__global__ void k_hfcvec(const float* __restrict__ out, const float* __restrict__ W1h,
                         const float* __restrict__ bh1) {
    __shared__ float red[256];
    const float* hf = out + (size_t)OFF_EMB + (size_t)NNODE*HID;
    int n = blockIdx.x;
    int t = threadIdx.x;
    if (n == 0) {
        if (t < 256) { g_hf[t] = hf[t]; g_hf[t + 256] = hf[t + 256]; }
    }
    float s = 0.f;
    for (int k = t; k < HID; k += 256)
        s += hf[k] * W1h[(size_t)k*512 + n];
    red[t] = s;
    __syncthreads();
    for (int st = 128; st; st >>= 1) {
        if (t < st) red[t] += red[t + st];
        __syncthreads();
    }
    if (t == 0) g_cvec[n] = red[0] + bh1[n];
}

// ----------------------------- launch 7: build Bm + split → gB1 ---------------
__global__ void k_buildsplit(const float* __restrict__ W1h) {
    int n = blockIdx.x;            // 0..511
    for (int k = threadIdx.x; k < 1024; k += blockDim.x) {
        float v = W1h[(size_t)(512 + k)*512 + n];
        if (k < 512) v += g_hf[k] * W1h[(size_t)(1536 + k)*512 + n];
        __nv_bfloat16 h, l; split_bf(v, h, l);
        gB1_hi[(size_t)n*1024 + k] = h;
        gB1_lo[(size_t)n*1024 + k] = l;
    }
}

// ----------------------------- launch 8: ef + X split -------------------------
__global__ void k_xef(float* __restrict__ out, const int* __restrict__ bch,
                      const float* __restrict__ tval, const float* __restrict__ isroot) {
    int u = blockIdx.x;
    int bc = bch[u];
    const float* ht = out + (size_t)OFF_EMB + (size_t)bc*512;
    float* ef = out + (size_t)OFF_EF + (size_t)u*2050;
    for (int j = threadIdx.x; j < 512; j += blockDim.x) {
        float h = ht[j], f = g_hf[j];
        float ab = fabsf(f - h), pr = f*h;
        ef[j] = f; ef[512 + j] = h; ef[1024 + j] = ab; ef[1536 + j] = pr;
        __nv_bfloat16 hh, hl, ah, al;
        split_bf(h, hh, hl); split_bf(ab, ah, al);
        gA_hi[(size_t)u*1024 + j]       = hh;
        gA_lo[(size_t)u*1024 + j]       = hl;
        gA_hi[(size_t)u*1024 + 512 + j] = ah;
        gA_lo[(size_t)u*1024 + 512 + j] = al;
    }
    if (threadIdx.x == 0) { ef[2048] = tval[u]; ef[2049] = isroot[u]; }
}

// ----------------------------- head ------------------------------------------
__global__ void k_logits(const float* __restrict__ W3, const float* __restrict__ b3,
                         float* __restrict__ out) {
    int w = (blockIdx.x * blockDim.x + threadIdx.x) >> 5;
    int lane = threadIdx.x & 31;
    if (w >= NNODE) return;
    const float* z = g_Z2 + (size_t)w*512;
    float s = 0.f;
    #pragma unroll 4
    for (int j = lane; j < 512; j += 32) s += z[j]*W3[j];
    #pragma unroll
    for (int off = 16; off; off >>= 1) s += __shfl_down_sync(0xffffffffu, s, off);
    if (lane == 0) out[w] = s + b3[0];
}

__global__ void k_softmax(float* __restrict__ out) {
    __shared__ float red[1024];
    int tid = threadIdx.x;
    float m = -1e30f;
    for (int i = tid; i < NNODE; i += 1024) m = fmaxf(m, out[i]);
    red[tid] = m; __syncthreads();
    for (int s = 512; s; s >>= 1) {
        if (tid < s) red[tid] = fmaxf(red[tid], red[tid + s]);
        __syncthreads();
    }
    float M = red[0]; __syncthreads();
    float sum = 0.f;
    for (int i = tid; i < NNODE; i += 1024) sum += __expf(out[i] - M);
    red[tid] = sum; __syncthreads();
    for (int s = 512; s; s >>= 1) {
        if (tid < s) red[tid] += red[tid + s];
        __syncthreads();
    }
    float inv = 1.f / red[0];
    for (int i = tid; i < NNODE; i += 1024)
        out[NNODE + i] = __expf(out[i] - M) * inv;
}

// ----------------------------- launcher --------------------------------------
extern "C" void kernel_launch(void* const* d_in, const int* in_sizes, int n_in,
                              void* d_out, int out_size) {
    const int*   ns     = (const int*)d_in[0];
    const int*   ch0    = (const int*)d_in[1];
    const int*   ch1    = (const int*)d_in[2];
    const int*   parent = (const int*)d_in[3];
    const int*   neigh  = (const int*)d_in[4];
    const int*   bch    = (const int*)d_in[5];
    const int*   focal  = (const int*)d_in[6];
    const float* tv     = (const float*)d_in[7];
    const float* isroot = (const float*)d_in[8];
    const float* W1     = (const float*)d_in[9];
    const float* b1     = (const float*)d_in[10];
    const float* W2     = (const float*)d_in[11];
    const float* b2     = (const float*)d_in[12];
    const float* Wh1    = (const float*)d_in[13];
    const float* bh1    = (const float*)d_in[14];
    const float* Wh2    = (const float*)d_in[15];
    const float* bh2    = (const float*)d_in[16];
    const float* Wh3    = (const float*)d_in[17];
    const float* bh3    = (const float*)d_in[18];
    float* out = (float*)d_out;

    dim3 gm(4, 64);
    k_prep<<<5121, 256>>>(W2, Wh2, ns, focal, W1, out);   // 1
    k_tree<<<512, 256>>>(ch0, ch1, parent);               // 2
    k_agg<<<NROW, 128>>>(0, neigh, b1);                   // 3
    k_agg<<<NROW, 128>>>(1, neigh, b1);                   // 4
    // 5 (profiled slot): GEMM0: emb = Agg(h) @ W2 + b2
    k_mma<<<gm, 256>>>(0, NROW, 512, b2,
                       nullptr, nullptr, nullptr, nullptr, out + OFF_EMB);
    k_hfcvec<<<512, 256>>>(out, Wh1, bh1);                // 6
    k_buildsplit<<<512, 256>>>(Wh1);                      // 7
    k_xef<<<NNODE, 256>>>(out, bch, tv, isroot);          // 8
    // 9: GEMM1
    k_mma<<<gm, 256>>>(1, NNODE, 1024, nullptr,
                       Wh1 + (size_t)2048*512, Wh1 + (size_t)2049*512,
                       tv, isroot, nullptr);
    // 10: GEMM2
    k_mma<<<gm, 256>>>(2, NNODE, 512, bh2,
                       nullptr, nullptr, nullptr, nullptr, nullptr);
    k_logits<<<256, 1024>>>(Wh3, bh3, out);               // 11
    k_softmax<<<1, 1024>>>(out);                          // 12
}